// round 5
// baseline (speedup 1.0000x reference)
#include <cuda_runtime.h>
#include <cstdint>

// Problem constants
#define D_IN   256
#define D_OUT  128
#define MAX_NODES 100000

// Scratch: support = input @ W + b   [N, D_OUT]  (51.2 MB, static device global)
// Referenced directly from kernels — no cudaGetSymbolAddress in kernel_launch.
__device__ float g_support[(size_t)MAX_NODES * D_OUT];

// ---------------------------------------------------------------------------
// Kernel 0: zero the output accumulator (d_out is poisoned to 0xAA)
// ---------------------------------------------------------------------------
__global__ __launch_bounds__(256) void zero_kernel(float* __restrict__ out, int n4)
{
    int idx = blockIdx.x * blockDim.x + threadIdx.x;
    int stride = gridDim.x * blockDim.x;
    float4* p = (float4*)out;
    float4 z = make_float4(0.f, 0.f, 0.f, 0.f);
    for (; idx < n4; idx += stride) p[idx] = z;
}

// ---------------------------------------------------------------------------
// Kernel 1: SGEMM  g_support[M,128] = A[M,256] @ W[256,128] + b
// 128x128 output tile per block, K-tile 16, 256 threads, 8x8 register tiles.
// ---------------------------------------------------------------------------
#define BM 128
#define BN 128
#define BK 16
#define TM 8
#define TN 8

__global__ __launch_bounds__(256) void gemm_bias_kernel(
    const float* __restrict__ A,   // [M, 256]
    const float* __restrict__ W,   // [256, 128]
    const float* __restrict__ b,   // [128]
    int M)
{
    __shared__ float As[BK][BM];   // k-major (transposed) for broadcast reads
    __shared__ float Bs[BK][BN];

    const int tid = threadIdx.x;
    const int block_row = blockIdx.x * BM;
    const int tm = (tid >> 4) * TM;   // 16 thread-rows
    const int tn = (tid & 15) * TN;   // 16 thread-cols

    float acc[TM][TN];
#pragma unroll
    for (int i = 0; i < TM; i++)
#pragma unroll
        for (int j = 0; j < TN; j++) acc[i][j] = 0.0f;

    for (int k0 = 0; k0 < D_IN; k0 += BK) {
        // Load A tile: 128 rows x 16 k = 512 float4, 2 per thread, transposed
#pragma unroll
        for (int s = tid; s < 512; s += 256) {
            const int r  = s >> 2;
            const int kq = (s & 3) * 4;
            const int grow = block_row + r;
            float4 v = make_float4(0.f, 0.f, 0.f, 0.f);
            if (grow < M)
                v = *(const float4*)(A + (size_t)grow * D_IN + k0 + kq);
            As[kq + 0][r] = v.x;
            As[kq + 1][r] = v.y;
            As[kq + 2][r] = v.z;
            As[kq + 3][r] = v.w;
        }
        // Load B tile: 16 k x 128 n = 512 float4, coalesced
#pragma unroll
        for (int s = tid; s < 512; s += 256) {
            const int kk = s >> 5;
            const int nq = (s & 31) * 4;
            *(float4*)&Bs[kk][nq] =
                *(const float4*)(W + (size_t)(k0 + kk) * D_OUT + nq);
        }
        __syncthreads();

#pragma unroll
        for (int kk = 0; kk < BK; kk++) {
            float ra[TM], rb[TN];
#pragma unroll
            for (int i = 0; i < TM; i++) ra[i] = As[kk][tm + i];
#pragma unroll
            for (int j = 0; j < TN; j++) rb[j] = Bs[kk][tn + j];
#pragma unroll
            for (int i = 0; i < TM; i++)
#pragma unroll
                for (int j = 0; j < TN; j++)
                    acc[i][j] = fmaf(ra[i], rb[j], acc[i][j]);
        }
        __syncthreads();
    }

    // Epilogue: add bias, store to g_support
    float bias[TN];
#pragma unroll
    for (int j = 0; j < TN; j++) bias[j] = b[tn + j];

#pragma unroll
    for (int i = 0; i < TM; i++) {
        const int grow = block_row + tm + i;
        if (grow < M) {
#pragma unroll
            for (int j4 = 0; j4 < TN; j4 += 4) {
                float4 v;
                v.x = acc[i][j4 + 0] + bias[j4 + 0];
                v.y = acc[i][j4 + 1] + bias[j4 + 1];
                v.z = acc[i][j4 + 2] + bias[j4 + 2];
                v.w = acc[i][j4 + 3] + bias[j4 + 3];
                *(float4*)(g_support + (size_t)grow * D_OUT + tn + j4) = v;
            }
        }
    }
}

// ---------------------------------------------------------------------------
// Kernel 2: edge scatter. One warp per edge.
// out[row[e], :] += val[e] * g_support[col[e], :]
// Lane handles one float4 (4 cols). red.global.add.v4.f32 -> REDG (no-return),
// 4x fewer L2 atomic ops than scalar atomicAdd.
// ---------------------------------------------------------------------------
__global__ __launch_bounds__(256) void edge_scatter_kernel(
    const int*   __restrict__ erow,
    const int*   __restrict__ ecol,
    const float* __restrict__ eval,
    float*       __restrict__ out,
    int E)
{
    const int warp = (int)((blockIdx.x * blockDim.x + threadIdx.x) >> 5);
    const int lane = threadIdx.x & 31;
    if (warp >= E) return;

    const int   r = erow[warp];
    const int   c = ecol[warp];
    const float v = eval[warp];

    float4 m = *(const float4*)(g_support + (size_t)c * D_OUT + lane * 4);
    m.x *= v; m.y *= v; m.z *= v; m.w *= v;

    float* dst = out + (size_t)r * D_OUT + lane * 4;
    asm volatile("red.global.add.v4.f32 [%0], {%1, %2, %3, %4};"
                 :: "l"(dst), "f"(m.x), "f"(m.y), "f"(m.z), "f"(m.w)
                 : "memory");
}

// ---------------------------------------------------------------------------
// Kernel 3: elementwise tanh in place
// ---------------------------------------------------------------------------
__global__ __launch_bounds__(256) void tanh_kernel(float* __restrict__ out, int n4)
{
    int idx = blockIdx.x * blockDim.x + threadIdx.x;
    int stride = gridDim.x * blockDim.x;
    float4* p = (float4*)out;
    for (; idx < n4; idx += stride) {
        float4 v = p[idx];
        v.x = tanhf(v.x);
        v.y = tanhf(v.y);
        v.z = tanhf(v.z);
        v.w = tanhf(v.w);
        p[idx] = v;
    }
}

// ---------------------------------------------------------------------------
// Launch. Pure kernel launches on stream 0 — graph-capturable, no allocs,
// no host runtime queries, deterministic.
// inputs: 0=input [N,256] f32, 1=edge_row [E] i32, 2=edge_col [E] i32,
//         3=edge_val [E] f32, 4=W [256,128] f32, 5=b [128] f32
// ---------------------------------------------------------------------------
extern "C" void kernel_launch(void* const* d_in, const int* in_sizes, int n_in,
                              void* d_out, int out_size)
{
    const float* input    = (const float*)d_in[0];
    const int*   edge_row = (const int*)  d_in[1];
    const int*   edge_col = (const int*)  d_in[2];
    const float* edge_val = (const float*)d_in[3];
    const float* W        = (const float*)d_in[4];
    const float* b        = (const float*)d_in[5];
    float*       out      = (float*)d_out;

    const int M = in_sizes[0] / D_IN;   // 100000
    const int E = in_sizes[1];          // 1600000
    const int n4 = out_size / 4;        // float4 count of output

    // 1) zero the accumulator
    zero_kernel<<<(n4 + 255) / 256, 256, 0, 0>>>(out, n4);

    // 2) support = input @ W + b
    gemm_bias_kernel<<<(M + BM - 1) / BM, 256, 0, 0>>>(input, W, b, M);

    // 3) scatter edges with vector reductions
    {
        const long long total_threads = (long long)E * 32;
        const int blocks = (int)((total_threads + 255) / 256);
        edge_scatter_kernel<<<blocks, 256, 0, 0>>>(edge_row, edge_col, edge_val,
                                                   out, E);
    }

    // 4) tanh in place
    tanh_kernel<<<(n4 + 255) / 256, 256, 0, 0>>>(out, n4);
}

// round 6
// speedup vs baseline: 1.3395x; 1.3395x over previous
#include <cuda_runtime.h>
#include <cstdint>

// Problem constants
#define D_IN   256
#define D_OUT  128
#define MAX_NODES 100000
#define MAX_EDGES 1600000

#define NB_SCAN ((MAX_NODES + 1023) / 1024)   // 98 scan blocks

// Static device scratch (no allocations anywhere)
__device__ float g_support[(size_t)MAX_NODES * D_OUT];   // X@W+b
__device__ int   g_cnt[MAX_NODES];                       // per-row degree
__device__ int   g_rowstart[MAX_NODES];                  // exclusive prefix
__device__ int   g_cur[MAX_NODES];                       // build cursor
__device__ int   g_partial[NB_SCAN];                     // scan block sums
__device__ int   g_ecol2[MAX_EDGES];                     // CSR-permuted cols
__device__ float g_eval2[MAX_EDGES];                     // CSR-permuted vals

// ---------------------------------------------------------------------------
// Kernel 1: SGEMM  g_support[M,128] = A[M,256] @ W[256,128] + b
// (fp32 FFMA-roofline bound; unchanged from round 5)
// ---------------------------------------------------------------------------
#define BM 128
#define BN 128
#define BK 16
#define TM 8
#define TN 8

__global__ __launch_bounds__(256) void gemm_bias_kernel(
    const float* __restrict__ A,
    const float* __restrict__ W,
    const float* __restrict__ b,
    int M)
{
    __shared__ float As[BK][BM];
    __shared__ float Bs[BK][BN];

    const int tid = threadIdx.x;
    const int block_row = blockIdx.x * BM;
    const int tm = (tid >> 4) * TM;
    const int tn = (tid & 15) * TN;

    float acc[TM][TN];
#pragma unroll
    for (int i = 0; i < TM; i++)
#pragma unroll
        for (int j = 0; j < TN; j++) acc[i][j] = 0.0f;

    for (int k0 = 0; k0 < D_IN; k0 += BK) {
#pragma unroll
        for (int s = tid; s < 512; s += 256) {
            const int r  = s >> 2;
            const int kq = (s & 3) * 4;
            const int grow = block_row + r;
            float4 v = make_float4(0.f, 0.f, 0.f, 0.f);
            if (grow < M)
                v = *(const float4*)(A + (size_t)grow * D_IN + k0 + kq);
            As[kq + 0][r] = v.x;
            As[kq + 1][r] = v.y;
            As[kq + 2][r] = v.z;
            As[kq + 3][r] = v.w;
        }
#pragma unroll
        for (int s = tid; s < 512; s += 256) {
            const int kk = s >> 5;
            const int nq = (s & 31) * 4;
            *(float4*)&Bs[kk][nq] =
                *(const float4*)(W + (size_t)(k0 + kk) * D_OUT + nq);
        }
        __syncthreads();

#pragma unroll
        for (int kk = 0; kk < BK; kk++) {
            float ra[TM], rb[TN];
#pragma unroll
            for (int i = 0; i < TM; i++) ra[i] = As[kk][tm + i];
#pragma unroll
            for (int j = 0; j < TN; j++) rb[j] = Bs[kk][tn + j];
#pragma unroll
            for (int i = 0; i < TM; i++)
#pragma unroll
                for (int j = 0; j < TN; j++)
                    acc[i][j] = fmaf(ra[i], rb[j], acc[i][j]);
        }
        __syncthreads();
    }

    float bias[TN];
#pragma unroll
    for (int j = 0; j < TN; j++) bias[j] = b[tn + j];

#pragma unroll
    for (int i = 0; i < TM; i++) {
        const int grow = block_row + tm + i;
        if (grow < M) {
#pragma unroll
            for (int j4 = 0; j4 < TN; j4 += 4) {
                float4 v;
                v.x = acc[i][j4 + 0] + bias[j4 + 0];
                v.y = acc[i][j4 + 1] + bias[j4 + 1];
                v.z = acc[i][j4 + 2] + bias[j4 + 2];
                v.w = acc[i][j4 + 3] + bias[j4 + 3];
                *(float4*)(g_support + (size_t)grow * D_OUT + tn + j4) = v;
            }
        }
    }
}

// ---------------------------------------------------------------------------
// CSR construction: zero counts -> histogram -> 3-phase exclusive scan ->
// permute edges into row-grouped order.
// ---------------------------------------------------------------------------
__global__ __launch_bounds__(256) void zero_cnt_kernel(int M)
{
    int i = blockIdx.x * blockDim.x + threadIdx.x;
    if (i < M) g_cnt[i] = 0;
}

__global__ __launch_bounds__(256) void hist_kernel(
    const int* __restrict__ erow, int E)
{
    int i = blockIdx.x * blockDim.x + threadIdx.x;
    int stride = gridDim.x * blockDim.x;
    for (; i < E; i += stride)
        atomicAdd(&g_cnt[erow[i]], 1);
}

// Phase 1: per-block (1024 elems) sums
__global__ __launch_bounds__(1024) void scan1_kernel(int M)
{
    __shared__ int s[1024];
    const int t = threadIdx.x;
    const int i = blockIdx.x * 1024 + t;
    int x = (i < M) ? g_cnt[i] : 0;
    s[t] = x;
    __syncthreads();
#pragma unroll
    for (int off = 512; off > 0; off >>= 1) {
        if (t < off) s[t] += s[t + off];
        __syncthreads();
    }
    if (t == 0) g_partial[blockIdx.x] = s[0];
}

// Phase 2: serial exclusive scan of the NB_SCAN block sums (tiny)
__global__ void scan2_kernel(int nb)
{
    if (threadIdx.x == 0) {
        int run = 0;
        for (int i = 0; i < nb; i++) {
            int v = g_partial[i];
            g_partial[i] = run;
            run += v;
        }
    }
}

// Phase 3: block-local exclusive scan + block offset
__global__ __launch_bounds__(1024) void scan3_kernel(int M)
{
    __shared__ int s[1024];
    const int t = threadIdx.x;
    const int i = blockIdx.x * 1024 + t;
    int x = (i < M) ? g_cnt[i] : 0;
    s[t] = x;
    __syncthreads();
    // Hillis-Steele inclusive scan
#pragma unroll
    for (int off = 1; off < 1024; off <<= 1) {
        int v = (t >= off) ? s[t - off] : 0;
        __syncthreads();
        s[t] += v;
        __syncthreads();
    }
    if (i < M) {
        int excl = g_partial[blockIdx.x] + s[t] - x;
        g_rowstart[i] = excl;
        g_cur[i]      = excl;
    }
}

// Permute edges into row-grouped CSR arrays
__global__ __launch_bounds__(256) void build_kernel(
    const int*   __restrict__ erow,
    const int*   __restrict__ ecol,
    const float* __restrict__ eval,
    int E)
{
    int i = blockIdx.x * blockDim.x + threadIdx.x;
    int stride = gridDim.x * blockDim.x;
    for (; i < E; i += stride) {
        int r = erow[i];
        int pos = atomicAdd(&g_cur[r], 1);
        g_ecol2[pos] = ecol[i];
        g_eval2[pos] = eval[i];
    }
}

// ---------------------------------------------------------------------------
// Aggregation: one warp per row. Lanes hold the 128-col row accumulator as
// float4. Gather support[col] (L2-resident) per edge, FMA, then tanh+store.
// No atomics, no separate zero/tanh kernels.
// ---------------------------------------------------------------------------
__global__ __launch_bounds__(256) void row_agg_kernel(
    float* __restrict__ out, int M)
{
    const int row  = (int)((blockIdx.x * blockDim.x + threadIdx.x) >> 5);
    const int lane = threadIdx.x & 31;
    if (row >= M) return;

    const int start = g_rowstart[row];
    const int deg   = g_cnt[row];
    const int end   = start + deg;

    float4 acc = make_float4(0.f, 0.f, 0.f, 0.f);

    int e = start;
    // 2x unroll: two independent gathers in flight per warp
    for (; e + 1 < end; e += 2) {
        const int   c0 = g_ecol2[e];
        const int   c1 = g_ecol2[e + 1];
        const float v0 = g_eval2[e];
        const float v1 = g_eval2[e + 1];
        float4 m0 = *(const float4*)(g_support + (size_t)c0 * D_OUT + lane * 4);
        float4 m1 = *(const float4*)(g_support + (size_t)c1 * D_OUT + lane * 4);
        acc.x = fmaf(v0, m0.x, acc.x); acc.y = fmaf(v0, m0.y, acc.y);
        acc.z = fmaf(v0, m0.z, acc.z); acc.w = fmaf(v0, m0.w, acc.w);
        acc.x = fmaf(v1, m1.x, acc.x); acc.y = fmaf(v1, m1.y, acc.y);
        acc.z = fmaf(v1, m1.z, acc.z); acc.w = fmaf(v1, m1.w, acc.w);
    }
    if (e < end) {
        const int   c0 = g_ecol2[e];
        const float v0 = g_eval2[e];
        float4 m0 = *(const float4*)(g_support + (size_t)c0 * D_OUT + lane * 4);
        acc.x = fmaf(v0, m0.x, acc.x); acc.y = fmaf(v0, m0.y, acc.y);
        acc.z = fmaf(v0, m0.z, acc.z); acc.w = fmaf(v0, m0.w, acc.w);
    }

    float4 r;
    r.x = tanhf(acc.x);
    r.y = tanhf(acc.y);
    r.z = tanhf(acc.z);
    r.w = tanhf(acc.w);
    *(float4*)(out + (size_t)row * D_OUT + lane * 4) = r;
}

// ---------------------------------------------------------------------------
// Launch. Pure kernel launches on stream 0 — graph-capturable, no allocs.
// inputs: 0=input [N,256] f32, 1=edge_row [E] i32, 2=edge_col [E] i32,
//         3=edge_val [E] f32, 4=W [256,128] f32, 5=b [128] f32
// ---------------------------------------------------------------------------
extern "C" void kernel_launch(void* const* d_in, const int* in_sizes, int n_in,
                              void* d_out, int out_size)
{
    const float* input    = (const float*)d_in[0];
    const int*   edge_row = (const int*)  d_in[1];
    const int*   edge_col = (const int*)  d_in[2];
    const float* edge_val = (const float*)d_in[3];
    const float* W        = (const float*)d_in[4];
    const float* b        = (const float*)d_in[5];
    float*       out      = (float*)d_out;

    const int M = in_sizes[0] / D_IN;   // 100000
    const int E = in_sizes[1];          // 1600000
    const int nb = (M + 1023) / 1024;   // scan blocks

    // CSR build (independent of GEMM, but same stream)
    zero_cnt_kernel<<<(M + 255) / 256, 256, 0, 0>>>(M);
    hist_kernel<<<1184, 256, 0, 0>>>(edge_row, E);
    scan1_kernel<<<nb, 1024, 0, 0>>>(M);
    scan2_kernel<<<1, 32, 0, 0>>>(nb);
    scan3_kernel<<<nb, 1024, 0, 0>>>(M);
    build_kernel<<<1184, 256, 0, 0>>>(edge_row, edge_col, edge_val, E);

    // Dense: support = input @ W + b
    gemm_bias_kernel<<<(M + BM - 1) / BM, 256, 0, 0>>>(input, W, b, M);

    // Aggregate + tanh + store (warp per row)
    {
        const long long total_threads = (long long)M * 32;
        const int blocks = (int)((total_threads + 255) / 256);
        row_agg_kernel<<<blocks, 256, 0, 0>>>(out, M);
    }
}

// round 7
// speedup vs baseline: 1.6931x; 1.2640x over previous
#include <cuda_runtime.h>
#include <cuda_bf16.h>
#include <cstdint>

// Problem constants
#define D_IN   256
#define D_OUT  128
#define MAX_NODES 100000
#define MAX_EDGES 1600000

#define NB_SCAN ((MAX_NODES + 1023) / 1024)   // 98 scan blocks

// Static device scratch (no allocations anywhere)
__device__ float g_support[(size_t)MAX_NODES * D_OUT];   // X@W+b
__device__ int   g_cnt[MAX_NODES];                       // per-row degree
__device__ int   g_rowstart[MAX_NODES];                  // exclusive prefix
__device__ int   g_cur[MAX_NODES];                       // build cursor
__device__ int   g_partial[NB_SCAN];                     // scan block sums
__device__ int   g_ecol2[MAX_EDGES];                     // CSR-permuted cols
__device__ float g_eval2[MAX_EDGES];                     // CSR-permuted vals

// ---------------------------------------------------------------------------
// Split-bf16 tensor-core GEMM:
//   g_support[M,128] = A[M,256] @ W[256,128] + b
// a = a_hi + a_lo (bf16 each); result = hi*hi + hi*lo + lo*hi (fp32 accum).
// Block tile 128x128, K-step 32 fp32. 256 threads = 8 warps (4m x 2n),
// warp tile 32x64, mma.sync.m16n8k16.bf16.
// ---------------------------------------------------------------------------
#define BM 128
#define BN 128
#define BKF 32            // fp32 k per mainloop iter
#define LDA 40            // As stride in bf16 elems (80B rows: conflict-free)
#define LDB 136           // Bs stride in bf16 elems (272B rows: conflict-free)

__device__ __forceinline__ uint32_t pack_bf16(__nv_bfloat16 lo, __nv_bfloat16 hi)
{
    return (uint32_t)__bfloat16_as_ushort(lo) |
           ((uint32_t)__bfloat16_as_ushort(hi) << 16);
}

__device__ __forceinline__ void ldmatrix_x4(uint32_t* r, const void* p)
{
    uint32_t a = (uint32_t)__cvta_generic_to_shared(p);
    asm volatile("ldmatrix.sync.aligned.m8n8.x4.shared.b16 {%0,%1,%2,%3}, [%4];"
                 : "=r"(r[0]), "=r"(r[1]), "=r"(r[2]), "=r"(r[3]) : "r"(a));
}

__device__ __forceinline__ void ldmatrix_x4_trans(uint32_t* r, const void* p)
{
    uint32_t a = (uint32_t)__cvta_generic_to_shared(p);
    asm volatile("ldmatrix.sync.aligned.m8n8.x4.trans.shared.b16 {%0,%1,%2,%3}, [%4];"
                 : "=r"(r[0]), "=r"(r[1]), "=r"(r[2]), "=r"(r[3]) : "r"(a));
}

__device__ __forceinline__ void mma_bf16(float* c, const uint32_t* a,
                                         uint32_t b0, uint32_t b1)
{
    asm volatile(
        "mma.sync.aligned.m16n8k16.row.col.f32.bf16.bf16.f32 "
        "{%0,%1,%2,%3}, {%4,%5,%6,%7}, {%8,%9}, {%0,%1,%2,%3};"
        : "+f"(c[0]), "+f"(c[1]), "+f"(c[2]), "+f"(c[3])
        : "r"(a[0]), "r"(a[1]), "r"(a[2]), "r"(a[3]), "r"(b0), "r"(b1));
}

__global__ __launch_bounds__(256) void gemm_bias_kernel(
    const float* __restrict__ A,   // [M, 256]
    const float* __restrict__ W,   // [256, 128]
    const float* __restrict__ b,   // [128]
    int M)
{
    __shared__ __nv_bfloat16 As_hi[BM * LDA];
    __shared__ __nv_bfloat16 As_lo[BM * LDA];
    __shared__ __nv_bfloat16 Bs_hi[BKF * LDB];
    __shared__ __nv_bfloat16 Bs_lo[BKF * LDB];

    const int tid  = threadIdx.x;
    const int lane = tid & 31;
    const int wid  = tid >> 5;
    const int wm   = (wid & 3) << 5;    // warp m offset: 0,32,64,96
    const int wn   = (wid >> 2) << 6;   // warp n offset: 0,64
    const int block_row = blockIdx.x * BM;

    float acc[2][8][4];
#pragma unroll
    for (int i = 0; i < 2; i++)
#pragma unroll
        for (int j = 0; j < 8; j++)
#pragma unroll
            for (int q = 0; q < 4; q++) acc[i][j][q] = 0.0f;

    for (int k0 = 0; k0 < D_IN; k0 += BKF) {
        // --- load + split A tile: 128 rows x 32 k = 1024 float4, 4/thread ---
#pragma unroll
        for (int t = 0; t < 4; t++) {
            const int s   = tid + t * 256;
            const int row = s >> 3;
            const int kq  = (s & 7) << 2;
            const int grow = block_row + row;
            float4 v = make_float4(0.f, 0.f, 0.f, 0.f);
            if (grow < M)
                v = *(const float4*)(A + (size_t)grow * D_IN + k0 + kq);
            __nv_bfloat16 h0 = __float2bfloat16(v.x);
            __nv_bfloat16 h1 = __float2bfloat16(v.y);
            __nv_bfloat16 h2 = __float2bfloat16(v.z);
            __nv_bfloat16 h3 = __float2bfloat16(v.w);
            __nv_bfloat16 l0 = __float2bfloat16(v.x - __bfloat162float(h0));
            __nv_bfloat16 l1 = __float2bfloat16(v.y - __bfloat162float(h1));
            __nv_bfloat16 l2 = __float2bfloat16(v.z - __bfloat162float(h2));
            __nv_bfloat16 l3 = __float2bfloat16(v.w - __bfloat162float(h3));
            uint32_t* ph = (uint32_t*)&As_hi[row * LDA + kq];
            uint32_t* pl = (uint32_t*)&As_lo[row * LDA + kq];
            ph[0] = pack_bf16(h0, h1); ph[1] = pack_bf16(h2, h3);
            pl[0] = pack_bf16(l0, l1); pl[1] = pack_bf16(l2, l3);
        }
        // --- load + split W tile: 32 k x 128 n = 1024 float4, 4/thread ---
#pragma unroll
        for (int t = 0; t < 4; t++) {
            const int s  = tid + t * 256;
            const int kk = s >> 5;
            const int n4 = (s & 31) << 2;
            float4 v = *(const float4*)(W + (size_t)(k0 + kk) * D_OUT + n4);
            __nv_bfloat16 h0 = __float2bfloat16(v.x);
            __nv_bfloat16 h1 = __float2bfloat16(v.y);
            __nv_bfloat16 h2 = __float2bfloat16(v.z);
            __nv_bfloat16 h3 = __float2bfloat16(v.w);
            __nv_bfloat16 l0 = __float2bfloat16(v.x - __bfloat162float(h0));
            __nv_bfloat16 l1 = __float2bfloat16(v.y - __bfloat162float(h1));
            __nv_bfloat16 l2 = __float2bfloat16(v.z - __bfloat162float(h2));
            __nv_bfloat16 l3 = __float2bfloat16(v.w - __bfloat162float(h3));
            uint32_t* ph = (uint32_t*)&Bs_hi[kk * LDB + n4];
            uint32_t* pl = (uint32_t*)&Bs_lo[kk * LDB + n4];
            ph[0] = pack_bf16(h0, h1); ph[1] = pack_bf16(h2, h3);
            pl[0] = pack_bf16(l0, l1); pl[1] = pack_bf16(l2, l3);
        }
        __syncthreads();

        // --- mma over two k16 chunks ---
#pragma unroll
        for (int kk = 0; kk < BKF; kk += 16) {
            uint32_t ah[2][4], al[2][4];
#pragma unroll
            for (int im = 0; im < 2; im++) {
                const int mrow = wm + (im << 4) + (lane & 15);
                const int kcol = kk + ((lane >> 4) << 3);
                ldmatrix_x4(ah[im], &As_hi[mrow * LDA + kcol]);
                ldmatrix_x4(al[im], &As_lo[mrow * LDA + kcol]);
            }
#pragma unroll
            for (int jn2 = 0; jn2 < 4; jn2++) {   // n16 chunks
                const int n0 = wn + (jn2 << 4);
                const int krow = kk + (lane & 15);
                const int ncol = n0 + ((lane >> 4) << 3);
                uint32_t bh[4], bl[4];
                ldmatrix_x4_trans(bh, &Bs_hi[krow * LDB + ncol]);
                ldmatrix_x4_trans(bl, &Bs_lo[krow * LDB + ncol]);
#pragma unroll
                for (int im = 0; im < 2; im++) {
#pragma unroll
                    for (int j = 0; j < 2; j++) {
                        float* c = acc[im][(jn2 << 1) + j];
                        mma_bf16(c, ah[im], bh[2 * j], bh[2 * j + 1]);
                        mma_bf16(c, ah[im], bl[2 * j], bl[2 * j + 1]);
                        mma_bf16(c, al[im], bh[2 * j], bh[2 * j + 1]);
                    }
                }
            }
        }
        __syncthreads();
    }

    // --- epilogue: bias + store to g_support ---
    const int rq = lane >> 2;        // 0..7
    const int c2 = (lane & 3) << 1;  // 0,2,4,6
#pragma unroll
    for (int jn = 0; jn < 8; jn++) {
        const int col = wn + (jn << 3) + c2;
        const float b0 = b[col];
        const float b1 = b[col + 1];
#pragma unroll
        for (int im = 0; im < 2; im++) {
#pragma unroll
            for (int h = 0; h < 2; h++) {
                const int row = block_row + wm + (im << 4) + rq + (h << 3);
                if (row < M) {
                    float2 v;
                    v.x = acc[im][jn][2 * h + 0] + b0;
                    v.y = acc[im][jn][2 * h + 1] + b1;
                    *(float2*)(g_support + (size_t)row * D_OUT + col) = v;
                }
            }
        }
    }
}

// ---------------------------------------------------------------------------
// CSR construction
// ---------------------------------------------------------------------------
__global__ __launch_bounds__(256) void zero_cnt_kernel(int M)
{
    int i = blockIdx.x * blockDim.x + threadIdx.x;
    if (i < M) g_cnt[i] = 0;
}

__global__ __launch_bounds__(256) void hist_kernel(
    const int* __restrict__ erow, int E)
{
    int i = blockIdx.x * blockDim.x + threadIdx.x;
    int stride = gridDim.x * blockDim.x;
    for (; i < E; i += stride)
        atomicAdd(&g_cnt[erow[i]], 1);
}

// Phase 1: per-block (1024 elems) sums
__global__ __launch_bounds__(1024) void scan1_kernel(int M)
{
    __shared__ int s[1024];
    const int t = threadIdx.x;
    const int i = blockIdx.x * 1024 + t;
    int x = (i < M) ? g_cnt[i] : 0;
    s[t] = x;
    __syncthreads();
#pragma unroll
    for (int off = 512; off > 0; off >>= 1) {
        if (t < off) s[t] += s[t + off];
        __syncthreads();
    }
    if (t == 0) g_partial[blockIdx.x] = s[0];
}

// Phase 2: parallel exclusive scan of block sums (nb <= 128)
__global__ __launch_bounds__(128) void scan2_kernel(int nb)
{
    __shared__ int s[128];
    const int t = threadIdx.x;
    int x = (t < nb) ? g_partial[t] : 0;
    s[t] = x;
    __syncthreads();
#pragma unroll
    for (int off = 1; off < 128; off <<= 1) {
        int v = (t >= off) ? s[t - off] : 0;
        __syncthreads();
        s[t] += v;
        __syncthreads();
    }
    if (t < nb) g_partial[t] = s[t] - x;   // exclusive
}

// Phase 3: block-local exclusive scan + block offset
__global__ __launch_bounds__(1024) void scan3_kernel(int M)
{
    __shared__ int s[1024];
    const int t = threadIdx.x;
    const int i = blockIdx.x * 1024 + t;
    int x = (i < M) ? g_cnt[i] : 0;
    s[t] = x;
    __syncthreads();
#pragma unroll
    for (int off = 1; off < 1024; off <<= 1) {
        int v = (t >= off) ? s[t - off] : 0;
        __syncthreads();
        s[t] += v;
        __syncthreads();
    }
    if (i < M) {
        int excl = g_partial[blockIdx.x] + s[t] - x;
        g_rowstart[i] = excl;
        g_cur[i]      = excl;
    }
}

__global__ __launch_bounds__(256) void build_kernel(
    const int*   __restrict__ erow,
    const int*   __restrict__ ecol,
    const float* __restrict__ eval,
    int E)
{
    int i = blockIdx.x * blockDim.x + threadIdx.x;
    int stride = gridDim.x * blockDim.x;
    for (; i < E; i += stride) {
        int r = erow[i];
        int pos = atomicAdd(&g_cur[r], 1);
        g_ecol2[pos] = ecol[i];
        g_eval2[pos] = eval[i];
    }
}

// ---------------------------------------------------------------------------
// Aggregation: one warp per row, float4 lane accumulators, fused tanh+store.
// ---------------------------------------------------------------------------
__global__ __launch_bounds__(256) void row_agg_kernel(
    float* __restrict__ out, int M)
{
    const int row  = (int)((blockIdx.x * blockDim.x + threadIdx.x) >> 5);
    const int lane = threadIdx.x & 31;
    if (row >= M) return;

    const int start = g_rowstart[row];
    const int end   = start + g_cnt[row];

    float4 acc = make_float4(0.f, 0.f, 0.f, 0.f);

    int e = start;
    for (; e + 1 < end; e += 2) {
        const int   c0 = g_ecol2[e];
        const int   c1 = g_ecol2[e + 1];
        const float v0 = g_eval2[e];
        const float v1 = g_eval2[e + 1];
        float4 m0 = *(const float4*)(g_support + (size_t)c0 * D_OUT + lane * 4);
        float4 m1 = *(const float4*)(g_support + (size_t)c1 * D_OUT + lane * 4);
        acc.x = fmaf(v0, m0.x, acc.x); acc.y = fmaf(v0, m0.y, acc.y);
        acc.z = fmaf(v0, m0.z, acc.z); acc.w = fmaf(v0, m0.w, acc.w);
        acc.x = fmaf(v1, m1.x, acc.x); acc.y = fmaf(v1, m1.y, acc.y);
        acc.z = fmaf(v1, m1.z, acc.z); acc.w = fmaf(v1, m1.w, acc.w);
    }
    if (e < end) {
        const int   c0 = g_ecol2[e];
        const float v0 = g_eval2[e];
        float4 m0 = *(const float4*)(g_support + (size_t)c0 * D_OUT + lane * 4);
        acc.x = fmaf(v0, m0.x, acc.x); acc.y = fmaf(v0, m0.y, acc.y);
        acc.z = fmaf(v0, m0.z, acc.z); acc.w = fmaf(v0, m0.w, acc.w);
    }

    float4 r;
    r.x = tanhf(acc.x);
    r.y = tanhf(acc.y);
    r.z = tanhf(acc.z);
    r.w = tanhf(acc.w);
    *(float4*)(out + (size_t)row * D_OUT + lane * 4) = r;
}

// ---------------------------------------------------------------------------
// Launch. Pure kernel launches on stream 0 — graph-capturable, no allocs.
// inputs: 0=input [N,256] f32, 1=edge_row [E] i32, 2=edge_col [E] i32,
//         3=edge_val [E] f32, 4=W [256,128] f32, 5=b [128] f32
// ---------------------------------------------------------------------------
extern "C" void kernel_launch(void* const* d_in, const int* in_sizes, int n_in,
                              void* d_out, int out_size)
{
    const float* input    = (const float*)d_in[0];
    const int*   edge_row = (const int*)  d_in[1];
    const int*   edge_col = (const int*)  d_in[2];
    const float* edge_val = (const float*)d_in[3];
    const float* W        = (const float*)d_in[4];
    const float* b        = (const float*)d_in[5];
    float*       out      = (float*)d_out;

    const int M = in_sizes[0] / D_IN;   // 100000
    const int E = in_sizes[1];          // 1600000
    const int nb = (M + 1023) / 1024;   // scan blocks (98)

    // CSR build
    zero_cnt_kernel<<<(M + 255) / 256, 256, 0, 0>>>(M);
    hist_kernel<<<1184, 256, 0, 0>>>(edge_row, E);
    scan1_kernel<<<nb, 1024, 0, 0>>>(M);
    scan2_kernel<<<1, 128, 0, 0>>>(nb);
    scan3_kernel<<<nb, 1024, 0, 0>>>(M);
    build_kernel<<<1184, 256, 0, 0>>>(edge_row, edge_col, edge_val, E);

    // Dense: support = input @ W + b  (split-bf16 tensor cores)
    gemm_bias_kernel<<<(M + BM - 1) / BM, 256, 0, 0>>>(input, W, b, M);

    // Aggregate + tanh + store (warp per row)
    {
        const long long total_threads = (long long)M * 32;
        const int blocks = (int)((total_threads + 255) / 256);
        row_agg_kernel<<<blocks, 256, 0, 0>>>(out, M);
    }
}

// round 11
// speedup vs baseline: 2.1771x; 1.2859x over previous
#include <cuda_runtime.h>
#include <cuda_bf16.h>
#include <cstdint>

// Problem constants
#define D_IN   256
#define D_OUT  128
#define MAX_NODES 100000
#define MAX_EDGES 1600000

#define NB_SCAN ((MAX_NODES + 1023) / 1024)   // 98 scan blocks

// Static device scratch (no allocations anywhere)
__device__ float g_support[(size_t)MAX_NODES * D_OUT];   // X@W+b
__device__ int   g_cnt[MAX_NODES];                       // per-row degree
__device__ int   g_rowstart[MAX_NODES];                  // exclusive prefix
__device__ int   g_cur[MAX_NODES];                       // build cursor
__device__ int   g_partial[NB_SCAN];                     // scan block sums
__device__ int   g_ecol2[MAX_EDGES];                     // CSR-permuted cols
__device__ float g_eval2[MAX_EDGES];                     // CSR-permuted vals

// ---------------------------------------------------------------------------
// Split-bf16 tensor-core GEMM, double-buffered pipeline:
//   g_support[M,128] = A[M,256] @ W[256,128] + b
// a = a_hi + a_lo (bf16); result = hi*hi + hi*lo + lo*hi (fp32 accum).
// Block tile 128x128, K-step 16, 16 mainloop iters, ping/pong smem,
// ONE __syncthreads per iter. 256 threads = 8 warps (4m x 2n), warp 32x64.
// ---------------------------------------------------------------------------
#define BM 128
#define BN 128
#define BK 16             // bf16 k per mainloop iter
#define NITER (D_IN / BK) // 16
#define LDA 24            // As row stride in bf16 elems (48B: conflict-free)
#define LDB 136           // Bs row stride in bf16 elems (272B: conflict-free)

// per-buffer element offsets within smem_buf[buf]
#define OFF_AH 0                    // 128*24 = 3072
#define OFF_AL 3072
#define OFF_BH 6144                 // 16*136 = 2176
#define OFF_BL 8320
#define BUF_ELEMS 10496             // 20992 B per buffer, x2 = 41984 B

__device__ __forceinline__ uint32_t pack_bf16(__nv_bfloat16 lo, __nv_bfloat16 hi)
{
    return (uint32_t)__bfloat16_as_ushort(lo) |
           ((uint32_t)__bfloat16_as_ushort(hi) << 16);
}

__device__ __forceinline__ void ldmatrix_x4(uint32_t* r, const void* p)
{
    uint32_t a = (uint32_t)__cvta_generic_to_shared(p);
    asm volatile("ldmatrix.sync.aligned.m8n8.x4.shared.b16 {%0,%1,%2,%3}, [%4];"
                 : "=r"(r[0]), "=r"(r[1]), "=r"(r[2]), "=r"(r[3]) : "r"(a));
}

__device__ __forceinline__ void ldmatrix_x4_trans(uint32_t* r, const void* p)
{
    uint32_t a = (uint32_t)__cvta_generic_to_shared(p);
    asm volatile("ldmatrix.sync.aligned.m8n8.x4.trans.shared.b16 {%0,%1,%2,%3}, [%4];"
                 : "=r"(r[0]), "=r"(r[1]), "=r"(r[2]), "=r"(r[3]) : "r"(a));
}

__device__ __forceinline__ void mma_bf16(float* c, const uint32_t* a,
                                         uint32_t b0, uint32_t b1)
{
    asm volatile(
        "mma.sync.aligned.m16n8k16.row.col.f32.bf16.bf16.f32 "
        "{%0,%1,%2,%3}, {%4,%5,%6,%7}, {%8,%9}, {%0,%1,%2,%3};"
        : "+f"(c[0]), "+f"(c[1]), "+f"(c[2]), "+f"(c[3])
        : "r"(a[0]), "r"(a[1]), "r"(a[2]), "r"(a[3]), "r"(b0), "r"(b1));
}

// split one float4 into packed-bf16 hi/lo pairs
__device__ __forceinline__ void split4(const float4& v, uint32_t* hi, uint32_t* lo)
{
    __nv_bfloat16 h0 = __float2bfloat16(v.x);
    __nv_bfloat16 h1 = __float2bfloat16(v.y);
    __nv_bfloat16 h2 = __float2bfloat16(v.z);
    __nv_bfloat16 h3 = __float2bfloat16(v.w);
    __nv_bfloat16 l0 = __float2bfloat16(v.x - __bfloat162float(h0));
    __nv_bfloat16 l1 = __float2bfloat16(v.y - __bfloat162float(h1));
    __nv_bfloat16 l2 = __float2bfloat16(v.z - __bfloat162float(h2));
    __nv_bfloat16 l3 = __float2bfloat16(v.w - __bfloat162float(h3));
    hi[0] = pack_bf16(h0, h1); hi[1] = pack_bf16(h2, h3);
    lo[0] = pack_bf16(l0, l1); lo[1] = pack_bf16(l2, l3);
}

__global__ __launch_bounds__(256) void gemm_bias_kernel(
    const float* __restrict__ A,   // [M, 256]
    const float* __restrict__ W,   // [256, 128]
    const float* __restrict__ b,   // [128]
    int M)
{
    __shared__ __nv_bfloat16 smem_buf[2][BUF_ELEMS];

    const int tid  = threadIdx.x;
    const int lane = tid & 31;
    const int wid  = tid >> 5;
    const int wm   = (wid & 3) << 5;    // warp m: 0,32,64,96
    const int wn   = (wid >> 2) << 6;   // warp n: 0,64
    const int block_row = blockIdx.x * BM;

    // per-thread load coords (constant across iters)
    const int a_row0 = tid >> 2;              // s = tid
    const int a_kq0  = (tid & 3) << 2;
    const int a_row1 = (tid + 256) >> 2;      // s = tid+256
    const int a_kq1  = ((tid + 256) & 3) << 2;
    const int b_kk0  = tid >> 5;
    const int b_n40  = (tid & 31) << 2;
    const int b_kk1  = (tid + 256) >> 5;
    const int b_n41  = ((tid + 256) & 31) << 2;

    const bool a_ok0 = (block_row + a_row0) < M;
    const bool a_ok1 = (block_row + a_row1) < M;
    const float* a_ptr0 = A + (size_t)(block_row + a_row0) * D_IN + a_kq0;
    const float* a_ptr1 = A + (size_t)(block_row + a_row1) * D_IN + a_kq1;
    const float* b_ptr0 = W + (size_t)b_kk0 * D_OUT + b_n40;
    const float* b_ptr1 = W + (size_t)b_kk1 * D_OUT + b_n41;

    float acc[2][8][4];
#pragma unroll
    for (int i = 0; i < 2; i++)
#pragma unroll
        for (int j = 0; j < 8; j++)
#pragma unroll
            for (int q = 0; q < 4; q++) acc[i][j][q] = 0.0f;

    float4 ra0, ra1, rb0, rb1;   // pipeline registers

    // ---- G2R for tile 0 ----
    ra0 = a_ok0 ? *(const float4*)(a_ptr0) : make_float4(0.f,0.f,0.f,0.f);
    ra1 = a_ok1 ? *(const float4*)(a_ptr1) : make_float4(0.f,0.f,0.f,0.f);
    rb0 = *(const float4*)(b_ptr0);
    rb1 = *(const float4*)(b_ptr1);

    // ---- R2S into buffer 0 ----
    {
        __nv_bfloat16* buf = smem_buf[0];
        uint32_t h[2], l[2];
        split4(ra0, h, l);
        ((uint32_t*)&buf[OFF_AH + a_row0 * LDA + a_kq0])[0] = h[0];
        ((uint32_t*)&buf[OFF_AH + a_row0 * LDA + a_kq0])[1] = h[1];
        ((uint32_t*)&buf[OFF_AL + a_row0 * LDA + a_kq0])[0] = l[0];
        ((uint32_t*)&buf[OFF_AL + a_row0 * LDA + a_kq0])[1] = l[1];
        split4(ra1, h, l);
        ((uint32_t*)&buf[OFF_AH + a_row1 * LDA + a_kq1])[0] = h[0];
        ((uint32_t*)&buf[OFF_AH + a_row1 * LDA + a_kq1])[1] = h[1];
        ((uint32_t*)&buf[OFF_AL + a_row1 * LDA + a_kq1])[0] = l[0];
        ((uint32_t*)&buf[OFF_AL + a_row1 * LDA + a_kq1])[1] = l[1];
        split4(rb0, h, l);
        ((uint32_t*)&buf[OFF_BH + b_kk0 * LDB + b_n40])[0] = h[0];
        ((uint32_t*)&buf[OFF_BH + b_kk0 * LDB + b_n40])[1] = h[1];
        ((uint32_t*)&buf[OFF_BL + b_kk0 * LDB + b_n40])[0] = l[0];
        ((uint32_t*)&buf[OFF_BL + b_kk0 * LDB + b_n40])[1] = l[1];
        split4(rb1, h, l);
        ((uint32_t*)&buf[OFF_BH + b_kk1 * LDB + b_n41])[0] = h[0];
        ((uint32_t*)&buf[OFF_BH + b_kk1 * LDB + b_n41])[1] = h[1];
        ((uint32_t*)&buf[OFF_BL + b_kk1 * LDB + b_n41])[0] = l[0];
        ((uint32_t*)&buf[OFF_BL + b_kk1 * LDB + b_n41])[1] = l[1];
    }
    __syncthreads();

#pragma unroll
    for (int it = 0; it < NITER; it++) {
        const int cur = it & 1;

        // ---- G2R for next tile (latency overlapped with MMA below) ----
        if (it + 1 < NITER) {
            const int k0 = (it + 1) * BK;
            ra0 = a_ok0 ? *(const float4*)(a_ptr0 + k0) : make_float4(0.f,0.f,0.f,0.f);
            ra1 = a_ok1 ? *(const float4*)(a_ptr1 + k0) : make_float4(0.f,0.f,0.f,0.f);
            rb0 = *(const float4*)(b_ptr0 + (size_t)k0 * D_OUT);
            rb1 = *(const float4*)(b_ptr1 + (size_t)k0 * D_OUT);
        }

        // ---- compute from buffer cur ----
        {
            const __nv_bfloat16* buf = smem_buf[cur];
            uint32_t ah[2][4], al[2][4];
#pragma unroll
            for (int im = 0; im < 2; im++) {
                const int mrow = wm + (im << 4) + (lane & 15);
                const int kcol = (lane >> 4) << 3;
                ldmatrix_x4(ah[im], &buf[OFF_AH + mrow * LDA + kcol]);
                ldmatrix_x4(al[im], &buf[OFF_AL + mrow * LDA + kcol]);
            }
#pragma unroll
            for (int jn2 = 0; jn2 < 4; jn2++) {
                const int krow = lane & 15;
                const int ncol = wn + (jn2 << 4) + ((lane >> 4) << 3);
                uint32_t bh[4], bl[4];
                ldmatrix_x4_trans(bh, &buf[OFF_BH + krow * LDB + ncol]);
                ldmatrix_x4_trans(bl, &buf[OFF_BL + krow * LDB + ncol]);
#pragma unroll
                for (int im = 0; im < 2; im++) {
#pragma unroll
                    for (int j = 0; j < 2; j++) {
                        float* c = acc[im][(jn2 << 1) + j];
                        mma_bf16(c, ah[im], bh[2 * j], bh[2 * j + 1]);
                        mma_bf16(c, ah[im], bl[2 * j], bl[2 * j + 1]);
                        mma_bf16(c, al[im], bh[2 * j], bh[2 * j + 1]);
                    }
                }
            }
        }

        // ---- R2S into other buffer; ONE barrier per iter ----
        if (it + 1 < NITER) {
            __nv_bfloat16* buf = smem_buf[cur ^ 1];
            uint32_t h[2], l[2];
            split4(ra0, h, l);
            ((uint32_t*)&buf[OFF_AH + a_row0 * LDA + a_kq0])[0] = h[0];
            ((uint32_t*)&buf[OFF_AH + a_row0 * LDA + a_kq0])[1] = h[1];
            ((uint32_t*)&buf[OFF_AL + a_row0 * LDA + a_kq0])[0] = l[0];
            ((uint32_t*)&buf[OFF_AL + a_row0 * LDA + a_kq0])[1] = l[1];
            split4(ra1, h, l);
            ((uint32_t*)&buf[OFF_AH + a_row1 * LDA + a_kq1])[0] = h[0];
            ((uint32_t*)&buf[OFF_AH + a_row1 * LDA + a_kq1])[1] = h[1];
            ((uint32_t*)&buf[OFF_AL + a_row1 * LDA + a_kq1])[0] = l[0];
            ((uint32_t*)&buf[OFF_AL + a_row1 * LDA + a_kq1])[1] = l[1];
            split4(rb0, h, l);
            ((uint32_t*)&buf[OFF_BH + b_kk0 * LDB + b_n40])[0] = h[0];
            ((uint32_t*)&buf[OFF_BH + b_kk0 * LDB + b_n40])[1] = h[1];
            ((uint32_t*)&buf[OFF_BL + b_kk0 * LDB + b_n40])[0] = l[0];
            ((uint32_t*)&buf[OFF_BL + b_kk0 * LDB + b_n40])[1] = l[1];
            split4(rb1, h, l);
            ((uint32_t*)&buf[OFF_BH + b_kk1 * LDB + b_n41])[0] = h[0];
            ((uint32_t*)&buf[OFF_BH + b_kk1 * LDB + b_n41])[1] = h[1];
            ((uint32_t*)&buf[OFF_BL + b_kk1 * LDB + b_n41])[0] = l[0];
            ((uint32_t*)&buf[OFF_BL + b_kk1 * LDB + b_n41])[1] = l[1];
            __syncthreads();
        }
    }

    // ---- epilogue: bias + store to g_support ----
    const int rq = lane >> 2;        // 0..7
    const int c2 = (lane & 3) << 1;  // 0,2,4,6
#pragma unroll
    for (int jn = 0; jn < 8; jn++) {
        const int col = wn + (jn << 3) + c2;
        const float b0 = b[col];
        const float b1 = b[col + 1];
#pragma unroll
        for (int im = 0; im < 2; im++) {
#pragma unroll
            for (int h = 0; h < 2; h++) {
                const int row = block_row + wm + (im << 4) + rq + (h << 3);
                if (row < M) {
                    float2 v;
                    v.x = acc[im][jn][2 * h + 0] + b0;
                    v.y = acc[im][jn][2 * h + 1] + b1;
                    *(float2*)(g_support + (size_t)row * D_OUT + col) = v;
                }
            }
        }
    }
}

// ---------------------------------------------------------------------------
// CSR construction
// ---------------------------------------------------------------------------
__global__ __launch_bounds__(256) void zero_cnt_kernel(int M)
{
    int i = blockIdx.x * blockDim.x + threadIdx.x;
    if (i < M) g_cnt[i] = 0;
}

__global__ __launch_bounds__(256) void hist_kernel(
    const int* __restrict__ erow, int E)
{
    int i = blockIdx.x * blockDim.x + threadIdx.x;
    int stride = gridDim.x * blockDim.x;
    for (; i < E; i += stride)
        atomicAdd(&g_cnt[erow[i]], 1);
}

// Phase 1: per-block (1024 elems) sums
__global__ __launch_bounds__(1024) void scan1_kernel(int M)
{
    __shared__ int s[1024];
    const int t = threadIdx.x;
    const int i = blockIdx.x * 1024 + t;
    int x = (i < M) ? g_cnt[i] : 0;
    s[t] = x;
    __syncthreads();
#pragma unroll
    for (int off = 512; off > 0; off >>= 1) {
        if (t < off) s[t] += s[t + off];
        __syncthreads();
    }
    if (t == 0) g_partial[blockIdx.x] = s[0];
}

// Phase 2 (fused): block-local scan + on-the-fly reduction of prior block sums
__global__ __launch_bounds__(1024) void scan3_kernel(int M, int nb)
{
    __shared__ int s[1024];
    __shared__ int red[128];
    __shared__ int s_boff;
    const int t = threadIdx.x;
    const int i = blockIdx.x * 1024 + t;

    // block offset = sum of g_partial[0 .. bid-1]   (nb <= 128)
    if (t < 128) {
        red[t] = (t < blockIdx.x && t < nb) ? g_partial[t] : 0;
    }
    int x = (i < M) ? g_cnt[i] : 0;
    s[t] = x;
    __syncthreads();
    if (t < 64) red[t] += red[t + 64];
    __syncthreads();
    if (t < 32) {
        int v = red[t] + red[t + 32];
#pragma unroll
        for (int off = 16; off > 0; off >>= 1)
            v += __shfl_down_sync(0xFFFFFFFFu, v, off);
        if (t == 0) s_boff = v;
    }
    // Hillis-Steele inclusive scan of this block's 1024 counts
#pragma unroll
    for (int off = 1; off < 1024; off <<= 1) {
        int v = (t >= off) ? s[t - off] : 0;
        __syncthreads();
        s[t] += v;
        __syncthreads();
    }
    if (i < M) {
        int excl = s_boff + s[t] - x;
        g_rowstart[i] = excl;
        g_cur[i]      = excl;
    }
}

__global__ __launch_bounds__(256) void build_kernel(
    const int*   __restrict__ erow,
    const int*   __restrict__ ecol,
    const float* __restrict__ eval,
    int E)
{
    int i = blockIdx.x * blockDim.x + threadIdx.x;
    int stride = gridDim.x * blockDim.x;
    for (; i < E; i += stride) {
        int r = erow[i];
        int pos = atomicAdd(&g_cur[r], 1);
        g_ecol2[pos] = ecol[i];
        g_eval2[pos] = eval[i];
    }
}

// ---------------------------------------------------------------------------
// Aggregation: one warp per row, float4 lane accumulators, 4x unrolled
// gathers (MLP=4), fused tanh + store.
// ---------------------------------------------------------------------------
__global__ __launch_bounds__(256) void row_agg_kernel(
    float* __restrict__ out, int M)
{
    const int row  = (int)((blockIdx.x * blockDim.x + threadIdx.x) >> 5);
    const int lane = threadIdx.x & 31;
    if (row >= M) return;

    const int start = g_rowstart[row];
    const int end   = start + g_cnt[row];
    const size_t loff = (size_t)(lane << 2);

    float4 acc = make_float4(0.f, 0.f, 0.f, 0.f);

    int e = start;
    for (; e + 3 < end; e += 4) {
        const int   c0 = g_ecol2[e];
        const int   c1 = g_ecol2[e + 1];
        const int   c2 = g_ecol2[e + 2];
        const int   c3 = g_ecol2[e + 3];
        const float v0 = g_eval2[e];
        const float v1 = g_eval2[e + 1];
        const float v2 = g_eval2[e + 2];
        const float v3 = g_eval2[e + 3];
        float4 m0 = *(const float4*)(g_support + (size_t)c0 * D_OUT + loff);
        float4 m1 = *(const float4*)(g_support + (size_t)c1 * D_OUT + loff);
        float4 m2 = *(const float4*)(g_support + (size_t)c2 * D_OUT + loff);
        float4 m3 = *(const float4*)(g_support + (size_t)c3 * D_OUT + loff);
        acc.x = fmaf(v0, m0.x, acc.x); acc.y = fmaf(v0, m0.y, acc.y);
        acc.z = fmaf(v0, m0.z, acc.z); acc.w = fmaf(v0, m0.w, acc.w);
        acc.x = fmaf(v1, m1.x, acc.x); acc.y = fmaf(v1, m1.y, acc.y);
        acc.z = fmaf(v1, m1.z, acc.z); acc.w = fmaf(v1, m1.w, acc.w);
        acc.x = fmaf(v2, m2.x, acc.x); acc.y = fmaf(v2, m2.y, acc.y);
        acc.z = fmaf(v2, m2.z, acc.z); acc.w = fmaf(v2, m2.w, acc.w);
        acc.x = fmaf(v3, m3.x, acc.x); acc.y = fmaf(v3, m3.y, acc.y);
        acc.z = fmaf(v3, m3.z, acc.z); acc.w = fmaf(v3, m3.w, acc.w);
    }
    for (; e < end; e++) {
        const int   c0 = g_ecol2[e];
        const float v0 = g_eval2[e];
        float4 m0 = *(const float4*)(g_support + (size_t)c0 * D_OUT + loff);
        acc.x = fmaf(v0, m0.x, acc.x); acc.y = fmaf(v0, m0.y, acc.y);
        acc.z = fmaf(v0, m0.z, acc.z); acc.w = fmaf(v0, m0.w, acc.w);
    }

    float4 r;
    r.x = tanhf(acc.x);
    r.y = tanhf(acc.y);
    r.z = tanhf(acc.z);
    r.w = tanhf(acc.w);
    *(float4*)(out + (size_t)row * D_OUT + loff) = r;
}

// ---------------------------------------------------------------------------
// Launch. Pure kernel launches on stream 0 — graph-capturable, no allocs.
// inputs: 0=input [N,256] f32, 1=edge_row [E] i32, 2=edge_col [E] i32,
//         3=edge_val [E] f32, 4=W [256,128] f32, 5=b [128] f32
// ---------------------------------------------------------------------------
extern "C" void kernel_launch(void* const* d_in, const int* in_sizes, int n_in,
                              void* d_out, int out_size)
{
    const float* input    = (const float*)d_in[0];
    const int*   edge_row = (const int*)  d_in[1];
    const int*   edge_col = (const int*)  d_in[2];
    const float* edge_val = (const float*)d_in[3];
    const float* W        = (const float*)d_in[4];
    const float* b        = (const float*)d_in[5];
    float*       out      = (float*)d_out;

    const int M = in_sizes[0] / D_IN;   // 100000
    const int E = in_sizes[1];          // 1600000
    const int nb = (M + 1023) / 1024;   // scan blocks (98)

    // CSR build
    zero_cnt_kernel<<<(M + 255) / 256, 256, 0, 0>>>(M);
    hist_kernel<<<1184, 256, 0, 0>>>(edge_row, E);
    scan1_kernel<<<nb, 1024, 0, 0>>>(M);
    scan3_kernel<<<nb, 1024, 0, 0>>>(M, nb);
    build_kernel<<<1184, 256, 0, 0>>>(edge_row, edge_col, edge_val, E);

    // Dense: support = input @ W + b  (split-bf16 tensor cores, pipelined)
    gemm_bias_kernel<<<(M + BM - 1) / BM, 256, 0, 0>>>(input, W, b, M);

    // Aggregate + tanh + store (warp per row)
    {
        const long long total_threads = (long long)M * 32;
        const int blocks = (int)((total_threads + 255) / 256);
        row_agg_kernel<<<blocks, 256, 0, 0>>>(out, M);
    }
}

// round 14
// speedup vs baseline: 2.2374x; 1.0277x over previous
#include <cuda_runtime.h>
#include <cuda_bf16.h>
#include <cuda_fp16.h>
#include <cstdint>

// Problem constants
#define D_IN   256
#define D_OUT  128
#define MAX_NODES 100000
#define MAX_EDGES 1600000

#define NB_SCAN ((MAX_NODES + 1023) / 1024)   // 98 scan blocks

// Static device scratch (no allocations anywhere)
__device__ __half g_support_h[(size_t)MAX_NODES * D_OUT]; // X@W+b (fp16)
__device__ int   g_cnt[MAX_NODES];                        // per-row degree
__device__ int   g_rowstart[MAX_NODES];                   // exclusive prefix
__device__ int   g_cur[MAX_NODES];                        // build cursor
__device__ int   g_partial[NB_SCAN];                      // scan block sums
__device__ int   g_ecol2[MAX_EDGES];                      // CSR-permuted cols
__device__ float g_eval2[MAX_EDGES];                      // CSR-permuted vals

// ---------------------------------------------------------------------------
// Split-bf16 tensor-core GEMM, double-buffered pipeline:
//   g_support_h[M,128] = fp16( A[M,256] @ W[256,128] + b )
// a = a_hi + a_lo (bf16); result = hi*hi + hi*lo + lo*hi (fp32 accum).
// Block tile 128x128, K-step 16, ping/pong smem, ONE __syncthreads per iter.
// 256 threads = 8 warps (4m x 2n), warp tile 32x64, mma.m16n8k16.bf16.
// ---------------------------------------------------------------------------
#define BM 128
#define BN 128
#define BK 16             // bf16 k per mainloop iter
#define NITER (D_IN / BK) // 16
#define LDA 24            // As row stride in bf16 elems (48B: conflict-free)
#define LDB 136           // Bs row stride in bf16 elems (272B: conflict-free)

#define OFF_AH 0                    // 128*24 = 3072
#define OFF_AL 3072
#define OFF_BH 6144                 // 16*136 = 2176
#define OFF_BL 8320
#define BUF_ELEMS 10496             // 20992 B per buffer, x2 = 41984 B

__device__ __forceinline__ uint32_t pack_bf16(__nv_bfloat16 lo, __nv_bfloat16 hi)
{
    return (uint32_t)__bfloat16_as_ushort(lo) |
           ((uint32_t)__bfloat16_as_ushort(hi) << 16);
}

__device__ __forceinline__ void ldmatrix_x4(uint32_t* r, const void* p)
{
    uint32_t a = (uint32_t)__cvta_generic_to_shared(p);
    asm volatile("ldmatrix.sync.aligned.m8n8.x4.shared.b16 {%0,%1,%2,%3}, [%4];"
                 : "=r"(r[0]), "=r"(r[1]), "=r"(r[2]), "=r"(r[3]) : "r"(a));
}

__device__ __forceinline__ void ldmatrix_x4_trans(uint32_t* r, const void* p)
{
    uint32_t a = (uint32_t)__cvta_generic_to_shared(p);
    asm volatile("ldmatrix.sync.aligned.m8n8.x4.trans.shared.b16 {%0,%1,%2,%3}, [%4];"
                 : "=r"(r[0]), "=r"(r[1]), "=r"(r[2]), "=r"(r[3]) : "r"(a));
}

__device__ __forceinline__ void mma_bf16(float* c, const uint32_t* a,
                                         uint32_t b0, uint32_t b1)
{
    asm volatile(
        "mma.sync.aligned.m16n8k16.row.col.f32.bf16.bf16.f32 "
        "{%0,%1,%2,%3}, {%4,%5,%6,%7}, {%8,%9}, {%0,%1,%2,%3};"
        : "+f"(c[0]), "+f"(c[1]), "+f"(c[2]), "+f"(c[3])
        : "r"(a[0]), "r"(a[1]), "r"(a[2]), "r"(a[3]), "r"(b0), "r"(b1));
}

__device__ __forceinline__ void split4(const float4& v, uint32_t* hi, uint32_t* lo)
{
    __nv_bfloat16 h0 = __float2bfloat16(v.x);
    __nv_bfloat16 h1 = __float2bfloat16(v.y);
    __nv_bfloat16 h2 = __float2bfloat16(v.z);
    __nv_bfloat16 h3 = __float2bfloat16(v.w);
    __nv_bfloat16 l0 = __float2bfloat16(v.x - __bfloat162float(h0));
    __nv_bfloat16 l1 = __float2bfloat16(v.y - __bfloat162float(h1));
    __nv_bfloat16 l2 = __float2bfloat16(v.z - __bfloat162float(h2));
    __nv_bfloat16 l3 = __float2bfloat16(v.w - __bfloat162float(h3));
    hi[0] = pack_bf16(h0, h1); hi[1] = pack_bf16(h2, h3);
    lo[0] = pack_bf16(l0, l1); lo[1] = pack_bf16(l2, l3);
}

__global__ __launch_bounds__(256) void gemm_bias_kernel(
    const float* __restrict__ A,   // [M, 256]
    const float* __restrict__ W,   // [256, 128]
    const float* __restrict__ b,   // [128]
    int M)
{
    __shared__ __nv_bfloat16 smem_buf[2][BUF_ELEMS];

    const int tid  = threadIdx.x;
    const int lane = tid & 31;
    const int wid  = tid >> 5;
    const int wm   = (wid & 3) << 5;    // warp m: 0,32,64,96
    const int wn   = (wid >> 2) << 6;   // warp n: 0,64
    const int block_row = blockIdx.x * BM;

    const int a_row0 = tid >> 2;
    const int a_kq0  = (tid & 3) << 2;
    const int a_row1 = (tid + 256) >> 2;
    const int a_kq1  = ((tid + 256) & 3) << 2;
    const int b_kk0  = tid >> 5;
    const int b_n40  = (tid & 31) << 2;
    const int b_kk1  = (tid + 256) >> 5;
    const int b_n41  = ((tid + 256) & 31) << 2;

    const bool a_ok0 = (block_row + a_row0) < M;
    const bool a_ok1 = (block_row + a_row1) < M;
    const float* a_ptr0 = A + (size_t)(block_row + a_row0) * D_IN + a_kq0;
    const float* a_ptr1 = A + (size_t)(block_row + a_row1) * D_IN + a_kq1;
    const float* b_ptr0 = W + (size_t)b_kk0 * D_OUT + b_n40;
    const float* b_ptr1 = W + (size_t)b_kk1 * D_OUT + b_n41;

    float acc[2][8][4];
#pragma unroll
    for (int i = 0; i < 2; i++)
#pragma unroll
        for (int j = 0; j < 8; j++)
#pragma unroll
            for (int q = 0; q < 4; q++) acc[i][j][q] = 0.0f;

    float4 ra0, ra1, rb0, rb1;

    ra0 = a_ok0 ? *(const float4*)(a_ptr0) : make_float4(0.f,0.f,0.f,0.f);
    ra1 = a_ok1 ? *(const float4*)(a_ptr1) : make_float4(0.f,0.f,0.f,0.f);
    rb0 = *(const float4*)(b_ptr0);
    rb1 = *(const float4*)(b_ptr1);

    {
        __nv_bfloat16* buf = smem_buf[0];
        uint32_t h[2], l[2];
        split4(ra0, h, l);
        ((uint32_t*)&buf[OFF_AH + a_row0 * LDA + a_kq0])[0] = h[0];
        ((uint32_t*)&buf[OFF_AH + a_row0 * LDA + a_kq0])[1] = h[1];
        ((uint32_t*)&buf[OFF_AL + a_row0 * LDA + a_kq0])[0] = l[0];
        ((uint32_t*)&buf[OFF_AL + a_row0 * LDA + a_kq0])[1] = l[1];
        split4(ra1, h, l);
        ((uint32_t*)&buf[OFF_AH + a_row1 * LDA + a_kq1])[0] = h[0];
        ((uint32_t*)&buf[OFF_AH + a_row1 * LDA + a_kq1])[1] = h[1];
        ((uint32_t*)&buf[OFF_AL + a_row1 * LDA + a_kq1])[0] = l[0];
        ((uint32_t*)&buf[OFF_AL + a_row1 * LDA + a_kq1])[1] = l[1];
        split4(rb0, h, l);
        ((uint32_t*)&buf[OFF_BH + b_kk0 * LDB + b_n40])[0] = h[0];
        ((uint32_t*)&buf[OFF_BH + b_kk0 * LDB + b_n40])[1] = h[1];
        ((uint32_t*)&buf[OFF_BL + b_kk0 * LDB + b_n40])[0] = l[0];
        ((uint32_t*)&buf[OFF_BL + b_kk0 * LDB + b_n40])[1] = l[1];
        split4(rb1, h, l);
        ((uint32_t*)&buf[OFF_BH + b_kk1 * LDB + b_n41])[0] = h[0];
        ((uint32_t*)&buf[OFF_BH + b_kk1 * LDB + b_n41])[1] = h[1];
        ((uint32_t*)&buf[OFF_BL + b_kk1 * LDB + b_n41])[0] = l[0];
        ((uint32_t*)&buf[OFF_BL + b_kk1 * LDB + b_n41])[1] = l[1];
    }
    __syncthreads();

#pragma unroll
    for (int it = 0; it < NITER; it++) {
        const int cur = it & 1;

        if (it + 1 < NITER) {
            const int k0 = (it + 1) * BK;
            ra0 = a_ok0 ? *(const float4*)(a_ptr0 + k0) : make_float4(0.f,0.f,0.f,0.f);
            ra1 = a_ok1 ? *(const float4*)(a_ptr1 + k0) : make_float4(0.f,0.f,0.f,0.f);
            rb0 = *(const float4*)(b_ptr0 + (size_t)k0 * D_OUT);
            rb1 = *(const float4*)(b_ptr1 + (size_t)k0 * D_OUT);
        }

        {
            const __nv_bfloat16* buf = smem_buf[cur];
            uint32_t ah[2][4], al[2][4];
#pragma unroll
            for (int im = 0; im < 2; im++) {
                const int mrow = wm + (im << 4) + (lane & 15);
                const int kcol = (lane >> 4) << 3;
                ldmatrix_x4(ah[im], &buf[OFF_AH + mrow * LDA + kcol]);
                ldmatrix_x4(al[im], &buf[OFF_AL + mrow * LDA + kcol]);
            }
#pragma unroll
            for (int jn2 = 0; jn2 < 4; jn2++) {
                const int krow = lane & 15;
                const int ncol = wn + (jn2 << 4) + ((lane >> 4) << 3);
                uint32_t bh[4], bl[4];
                ldmatrix_x4_trans(bh, &buf[OFF_BH + krow * LDB + ncol]);
                ldmatrix_x4_trans(bl, &buf[OFF_BL + krow * LDB + ncol]);
#pragma unroll
                for (int im = 0; im < 2; im++) {
#pragma unroll
                    for (int j = 0; j < 2; j++) {
                        float* c = acc[im][(jn2 << 1) + j];
                        mma_bf16(c, ah[im], bh[2 * j], bh[2 * j + 1]);
                        mma_bf16(c, ah[im], bl[2 * j], bl[2 * j + 1]);
                        mma_bf16(c, al[im], bh[2 * j], bh[2 * j + 1]);
                    }
                }
            }
        }

        if (it + 1 < NITER) {
            __nv_bfloat16* buf = smem_buf[cur ^ 1];
            uint32_t h[2], l[2];
            split4(ra0, h, l);
            ((uint32_t*)&buf[OFF_AH + a_row0 * LDA + a_kq0])[0] = h[0];
            ((uint32_t*)&buf[OFF_AH + a_row0 * LDA + a_kq0])[1] = h[1];
            ((uint32_t*)&buf[OFF_AL + a_row0 * LDA + a_kq0])[0] = l[0];
            ((uint32_t*)&buf[OFF_AL + a_row0 * LDA + a_kq0])[1] = l[1];
            split4(ra1, h, l);
            ((uint32_t*)&buf[OFF_AH + a_row1 * LDA + a_kq1])[0] = h[0];
            ((uint32_t*)&buf[OFF_AH + a_row1 * LDA + a_kq1])[1] = h[1];
            ((uint32_t*)&buf[OFF_AL + a_row1 * LDA + a_kq1])[0] = l[0];
            ((uint32_t*)&buf[OFF_AL + a_row1 * LDA + a_kq1])[1] = l[1];
            split4(rb0, h, l);
            ((uint32_t*)&buf[OFF_BH + b_kk0 * LDB + b_n40])[0] = h[0];
            ((uint32_t*)&buf[OFF_BH + b_kk0 * LDB + b_n40])[1] = h[1];
            ((uint32_t*)&buf[OFF_BL + b_kk0 * LDB + b_n40])[0] = l[0];
            ((uint32_t*)&buf[OFF_BL + b_kk0 * LDB + b_n40])[1] = l[1];
            split4(rb1, h, l);
            ((uint32_t*)&buf[OFF_BH + b_kk1 * LDB + b_n41])[0] = h[0];
            ((uint32_t*)&buf[OFF_BH + b_kk1 * LDB + b_n41])[1] = h[1];
            ((uint32_t*)&buf[OFF_BL + b_kk1 * LDB + b_n41])[0] = l[0];
            ((uint32_t*)&buf[OFF_BL + b_kk1 * LDB + b_n41])[1] = l[1];
            __syncthreads();
        }
    }

    // ---- epilogue: bias + fp16 store to g_support_h ----
    const int rq = lane >> 2;        // 0..7
    const int c2 = (lane & 3) << 1;  // 0,2,4,6
#pragma unroll
    for (int jn = 0; jn < 8; jn++) {
        const int col = wn + (jn << 3) + c2;
        const float b0 = b[col];
        const float b1 = b[col + 1];
#pragma unroll
        for (int im = 0; im < 2; im++) {
#pragma unroll
            for (int h = 0; h < 2; h++) {
                const int row = block_row + wm + (im << 4) + rq + (h << 3);
                if (row < M) {
                    __half2 v = __floats2half2_rn(acc[im][jn][2 * h + 0] + b0,
                                                  acc[im][jn][2 * h + 1] + b1);
                    *(__half2*)(g_support_h + (size_t)row * D_OUT + col) = v;
                }
            }
        }
    }
}

// ---------------------------------------------------------------------------
// CSR construction
// ---------------------------------------------------------------------------
__global__ __launch_bounds__(256) void zero_cnt_kernel(int M)
{
    int i = blockIdx.x * blockDim.x + threadIdx.x;
    if (i < M) g_cnt[i] = 0;
}

__global__ __launch_bounds__(256) void hist_kernel(
    const int* __restrict__ erow, int E)
{
    int i = blockIdx.x * blockDim.x + threadIdx.x;
    int stride = gridDim.x * blockDim.x;
    for (; i < E; i += stride)
        atomicAdd(&g_cnt[erow[i]], 1);
}

// Phase 1: per-block (1024 elems) sums
__global__ __launch_bounds__(1024) void scan1_kernel(int M)
{
    __shared__ int s[1024];
    const int t = threadIdx.x;
    const int i = blockIdx.x * 1024 + t;
    int x = (i < M) ? g_cnt[i] : 0;
    s[t] = x;
    __syncthreads();
#pragma unroll
    for (int off = 512; off > 0; off >>= 1) {
        if (t < off) s[t] += s[t + off];
        __syncthreads();
    }
    if (t == 0) g_partial[blockIdx.x] = s[0];
}

// Phase 2 (fused, shuffle-based): block-local exclusive scan + block offset.
// Warp-shuffle scans; warp 1 reduces prior block sums concurrently.
__global__ __launch_bounds__(1024) void scan3_kernel(int M, int nb)
{
    __shared__ int warp_sums[32];
    __shared__ int s_boff;

    const int t    = threadIdx.x;
    const int lane = t & 31;
    const int wid  = t >> 5;
    const int i    = blockIdx.x * 1024 + t;

    int x = (i < M) ? g_cnt[i] : 0;

    // warp-inclusive scan of x
    int inc = x;
#pragma unroll
    for (int off = 1; off < 32; off <<= 1) {
        int n = __shfl_up_sync(0xFFFFFFFFu, inc, off);
        if (lane >= off) inc += n;
    }
    if (lane == 31) warp_sums[wid] = inc;

    // warp 1: block offset = sum of g_partial[0 .. bid-1]  (bid <= 97)
    if (wid == 1) {
        int a = 0;
        for (int j = lane; j < blockIdx.x; j += 32) a += g_partial[j];
#pragma unroll
        for (int off = 16; off > 0; off >>= 1)
            a += __shfl_down_sync(0xFFFFFFFFu, a, off);
        if (lane == 0) s_boff = a;
    }
    __syncthreads();

    // warp 0: exclusive scan of the 32 warp sums
    if (wid == 0) {
        int ws = warp_sums[lane];
        int wsi = ws;
#pragma unroll
        for (int off = 1; off < 32; off <<= 1) {
            int n = __shfl_up_sync(0xFFFFFFFFu, wsi, off);
            if (lane >= off) wsi += n;
        }
        warp_sums[lane] = wsi - ws;
    }
    __syncthreads();

    if (i < M) {
        int excl = s_boff + warp_sums[wid] + inc - x;
        g_rowstart[i] = excl;
        g_cur[i]      = excl;
    }
}

__global__ __launch_bounds__(256) void build_kernel(
    const int*   __restrict__ erow,
    const int*   __restrict__ ecol,
    const float* __restrict__ eval,
    int E)
{
    int i = blockIdx.x * blockDim.x + threadIdx.x;
    int stride = gridDim.x * blockDim.x;
    for (; i < E; i += stride) {
        int r = erow[i];
        int pos = atomicAdd(&g_cur[r], 1);
        g_ecol2[pos] = ecol[i];
        g_eval2[pos] = eval[i];
    }
}

// ---------------------------------------------------------------------------
// Aggregation: one warp per row. Lane holds 4 cols (fp32 accum), gathers are
// 8B (4 fp16) per lane -> 256B per support row (half the fp32 traffic).
// 4x unrolled (MLP=4), fused tanh + fp32 store.
// ---------------------------------------------------------------------------
__global__ __launch_bounds__(256) void row_agg_kernel(
    float* __restrict__ out, int M)
{
    const int row  = (int)((blockIdx.x * blockDim.x + threadIdx.x) >> 5);
    const int lane = threadIdx.x & 31;
    if (row >= M) return;

    const int start = g_rowstart[row];
    const int end   = start + g_cnt[row];
    const size_t loff = (size_t)(lane << 2);   // 4 cols per lane

    float4 acc = make_float4(0.f, 0.f, 0.f, 0.f);

    int e = start;
    for (; e + 3 < end; e += 4) {
        const int   c0 = g_ecol2[e];
        const int   c1 = g_ecol2[e + 1];
        const int   c2 = g_ecol2[e + 2];
        const int   c3 = g_ecol2[e + 3];
        const float v0 = g_eval2[e];
        const float v1 = g_eval2[e + 1];
        const float v2 = g_eval2[e + 2];
        const float v3 = g_eval2[e + 3];
        uint2 u0 = *(const uint2*)(g_support_h + (size_t)c0 * D_OUT + loff);
        uint2 u1 = *(const uint2*)(g_support_h + (size_t)c1 * D_OUT + loff);
        uint2 u2 = *(const uint2*)(g_support_h + (size_t)c2 * D_OUT + loff);
        uint2 u3 = *(const uint2*)(g_support_h + (size_t)c3 * D_OUT + loff);
        float2 a0 = __half22float2(*(__half2*)&u0.x);
        float2 b0f = __half22float2(*(__half2*)&u0.y);
        float2 a1 = __half22float2(*(__half2*)&u1.x);
        float2 b1f = __half22float2(*(__half2*)&u1.y);
        float2 a2 = __half22float2(*(__half2*)&u2.x);
        float2 b2f = __half22float2(*(__half2*)&u2.y);
        float2 a3 = __half22float2(*(__half2*)&u3.x);
        float2 b3f = __half22float2(*(__half2*)&u3.y);
        acc.x = fmaf(v0, a0.x, acc.x); acc.y = fmaf(v0, a0.y, acc.y);
        acc.z = fmaf(v0, b0f.x, acc.z); acc.w = fmaf(v0, b0f.y, acc.w);
        acc.x = fmaf(v1, a1.x, acc.x); acc.y = fmaf(v1, a1.y, acc.y);
        acc.z = fmaf(v1, b1f.x, acc.z); acc.w = fmaf(v1, b1f.y, acc.w);
        acc.x = fmaf(v2, a2.x, acc.x); acc.y = fmaf(v2, a2.y, acc.y);
        acc.z = fmaf(v2, b2f.x, acc.z); acc.w = fmaf(v2, b2f.y, acc.w);
        acc.x = fmaf(v3, a3.x, acc.x); acc.y = fmaf(v3, a3.y, acc.y);
        acc.z = fmaf(v3, b3f.x, acc.z); acc.w = fmaf(v3, b3f.y, acc.w);
    }
    for (; e < end; e++) {
        const int   c0 = g_ecol2[e];
        const float v0 = g_eval2[e];
        uint2 u0 = *(const uint2*)(g_support_h + (size_t)c0 * D_OUT + loff);
        float2 a0 = __half22float2(*(__half2*)&u0.x);
        float2 b0f = __half22float2(*(__half2*)&u0.y);
        acc.x = fmaf(v0, a0.x, acc.x); acc.y = fmaf(v0, a0.y, acc.y);
        acc.z = fmaf(v0, b0f.x, acc.z); acc.w = fmaf(v0, b0f.y, acc.w);
    }

    float4 r;
    r.x = tanhf(acc.x);
    r.y = tanhf(acc.y);
    r.z = tanhf(acc.z);
    r.w = tanhf(acc.w);
    *(float4*)(out + (size_t)row * D_OUT + loff) = r;
}

// ---------------------------------------------------------------------------
// Launch. Pure kernel launches on stream 0 — graph-capturable, no allocs.
// inputs: 0=input [N,256] f32, 1=edge_row [E] i32, 2=edge_col [E] i32,
//         3=edge_val [E] f32, 4=W [256,128] f32, 5=b [128] f32
// ---------------------------------------------------------------------------
extern "C" void kernel_launch(void* const* d_in, const int* in_sizes, int n_in,
                              void* d_out, int out_size)
{
    const float* input    = (const float*)d_in[0];
    const int*   edge_row = (const int*)  d_in[1];
    const int*   edge_col = (const int*)  d_in[2];
    const float* edge_val = (const float*)d_in[3];
    const float* W        = (const float*)d_in[4];
    const float* b        = (const float*)d_in[5];
    float*       out      = (float*)d_out;

    const int M = in_sizes[0] / D_IN;   // 100000
    const int E = in_sizes[1];          // 1600000
    const int nb = (M + 1023) / 1024;   // scan blocks (98)

    // CSR build
    zero_cnt_kernel<<<(M + 255) / 256, 256, 0, 0>>>(M);
    hist_kernel<<<1184, 256, 0, 0>>>(edge_row, E);
    scan1_kernel<<<nb, 1024, 0, 0>>>(M);
    scan3_kernel<<<nb, 1024, 0, 0>>>(M, nb);
    build_kernel<<<1184, 256, 0, 0>>>(edge_row, edge_col, edge_val, E);

    // Dense: support = input @ W + b  (split-bf16 tensor cores -> fp16 out)
    gemm_bias_kernel<<<(M + BM - 1) / BM, 256, 0, 0>>>(input, W, b, M);

    // Aggregate + tanh + store (warp per row)
    {
        const long long total_threads = (long long)M * 32;
        const int blocks = (int)((total_threads + 255) / 256);
        row_agg_kernel<<<blocks, 256, 0, 0>>>(out, M);
    }
}

// round 15
// speedup vs baseline: 2.3696x; 1.0591x over previous
#include <cuda_runtime.h>
#include <cuda_fp16.h>
#include <cstdint>

// Problem constants
#define D_IN   256
#define D_OUT  128
#define MAX_NODES 100000
#define MAX_EDGES 1600000

#define NB_SCAN ((MAX_NODES + 1023) / 1024)   // 98 scan blocks

// Static device scratch (no allocations anywhere)
__device__ __half g_support_h[(size_t)MAX_NODES * D_OUT]; // X@W+b (fp16)
__device__ int   g_cnt[MAX_NODES];                        // per-row degree
__device__ int   g_rowstart[MAX_NODES];                   // exclusive prefix
__device__ int   g_cur[MAX_NODES];                        // build cursor
__device__ int   g_partial[NB_SCAN];                      // scan block sums
__device__ int2  g_epack[MAX_EDGES];                      // CSR {col, val_bits}

// ---------------------------------------------------------------------------
// fp16 tensor-core GEMM (single MMA), double-buffered pipeline:
//   g_support_h[M,128] = fp16( A[M,256] @ W[256,128] + b )
// Block tile 128x128, K-step 16, ping/pong smem, ONE __syncthreads per iter.
// 256 threads = 8 warps (4m x 2n), warp tile 32x64, mma.m16n8k16.f16.
// ---------------------------------------------------------------------------
#define BM 128
#define BN 128
#define BK 16             // k per mainloop iter
#define NITER (D_IN / BK) // 16
#define LDA 24            // As row stride in fp16 elems (48B: conflict-free)
#define LDB 136           // Bs row stride in fp16 elems (272B: conflict-free)

#define OFF_A 0                     // 128*24 = 3072
#define OFF_B 3072                  // 16*136 = 2176
#define BUF_ELEMS 5248              // 10496 B per buffer, x2 = 20992 B

__device__ __forceinline__ void ldmatrix_x4(uint32_t* r, const void* p)
{
    uint32_t a = (uint32_t)__cvta_generic_to_shared(p);
    asm volatile("ldmatrix.sync.aligned.m8n8.x4.shared.b16 {%0,%1,%2,%3}, [%4];"
                 : "=r"(r[0]), "=r"(r[1]), "=r"(r[2]), "=r"(r[3]) : "r"(a));
}

__device__ __forceinline__ void ldmatrix_x4_trans(uint32_t* r, const void* p)
{
    uint32_t a = (uint32_t)__cvta_generic_to_shared(p);
    asm volatile("ldmatrix.sync.aligned.m8n8.x4.trans.shared.b16 {%0,%1,%2,%3}, [%4];"
                 : "=r"(r[0]), "=r"(r[1]), "=r"(r[2]), "=r"(r[3]) : "r"(a));
}

__device__ __forceinline__ void mma_f16(float* c, const uint32_t* a,
                                        uint32_t b0, uint32_t b1)
{
    asm volatile(
        "mma.sync.aligned.m16n8k16.row.col.f32.f16.f16.f32 "
        "{%0,%1,%2,%3}, {%4,%5,%6,%7}, {%8,%9}, {%0,%1,%2,%3};"
        : "+f"(c[0]), "+f"(c[1]), "+f"(c[2]), "+f"(c[3])
        : "r"(a[0]), "r"(a[1]), "r"(a[2]), "r"(a[3]), "r"(b0), "r"(b1));
}

// convert float4 -> two packed half2 words
__device__ __forceinline__ void cvt4(const float4& v, uint32_t* h)
{
    __half2 p0 = __floats2half2_rn(v.x, v.y);
    __half2 p1 = __floats2half2_rn(v.z, v.w);
    h[0] = *(uint32_t*)&p0;
    h[1] = *(uint32_t*)&p1;
}

__global__ __launch_bounds__(256) void gemm_bias_kernel(
    const float* __restrict__ A,   // [M, 256]
    const float* __restrict__ W,   // [256, 128]
    const float* __restrict__ b,   // [128]
    int M)
{
    __shared__ __half smem_buf[2][BUF_ELEMS];

    const int tid  = threadIdx.x;
    const int lane = tid & 31;
    const int wid  = tid >> 5;
    const int wm   = (wid & 3) << 5;    // warp m: 0,32,64,96
    const int wn   = (wid >> 2) << 6;   // warp n: 0,64
    const int block_row = blockIdx.x * BM;

    const int a_row0 = tid >> 2;
    const int a_kq0  = (tid & 3) << 2;
    const int a_row1 = (tid + 256) >> 2;
    const int a_kq1  = ((tid + 256) & 3) << 2;
    const int b_kk0  = tid >> 5;
    const int b_n40  = (tid & 31) << 2;
    const int b_kk1  = (tid + 256) >> 5;
    const int b_n41  = ((tid + 256) & 31) << 2;

    const bool a_ok0 = (block_row + a_row0) < M;
    const bool a_ok1 = (block_row + a_row1) < M;
    const float* a_ptr0 = A + (size_t)(block_row + a_row0) * D_IN + a_kq0;
    const float* a_ptr1 = A + (size_t)(block_row + a_row1) * D_IN + a_kq1;
    const float* b_ptr0 = W + (size_t)b_kk0 * D_OUT + b_n40;
    const float* b_ptr1 = W + (size_t)b_kk1 * D_OUT + b_n41;

    float acc[2][8][4];
#pragma unroll
    for (int i = 0; i < 2; i++)
#pragma unroll
        for (int j = 0; j < 8; j++)
#pragma unroll
            for (int q = 0; q < 4; q++) acc[i][j][q] = 0.0f;

    float4 ra0, ra1, rb0, rb1;

    ra0 = a_ok0 ? *(const float4*)(a_ptr0) : make_float4(0.f,0.f,0.f,0.f);
    ra1 = a_ok1 ? *(const float4*)(a_ptr1) : make_float4(0.f,0.f,0.f,0.f);
    rb0 = *(const float4*)(b_ptr0);
    rb1 = *(const float4*)(b_ptr1);

    {
        __half* buf = smem_buf[0];
        uint32_t h[2];
        cvt4(ra0, h);
        ((uint32_t*)&buf[OFF_A + a_row0 * LDA + a_kq0])[0] = h[0];
        ((uint32_t*)&buf[OFF_A + a_row0 * LDA + a_kq0])[1] = h[1];
        cvt4(ra1, h);
        ((uint32_t*)&buf[OFF_A + a_row1 * LDA + a_kq1])[0] = h[0];
        ((uint32_t*)&buf[OFF_A + a_row1 * LDA + a_kq1])[1] = h[1];
        cvt4(rb0, h);
        ((uint32_t*)&buf[OFF_B + b_kk0 * LDB + b_n40])[0] = h[0];
        ((uint32_t*)&buf[OFF_B + b_kk0 * LDB + b_n40])[1] = h[1];
        cvt4(rb1, h);
        ((uint32_t*)&buf[OFF_B + b_kk1 * LDB + b_n41])[0] = h[0];
        ((uint32_t*)&buf[OFF_B + b_kk1 * LDB + b_n41])[1] = h[1];
    }
    __syncthreads();

#pragma unroll
    for (int it = 0; it < NITER; it++) {
        const int cur = it & 1;

        // G2R for next tile (latency overlapped with MMA below)
        if (it + 1 < NITER) {
            const int k0 = (it + 1) * BK;
            ra0 = a_ok0 ? *(const float4*)(a_ptr0 + k0) : make_float4(0.f,0.f,0.f,0.f);
            ra1 = a_ok1 ? *(const float4*)(a_ptr1 + k0) : make_float4(0.f,0.f,0.f,0.f);
            rb0 = *(const float4*)(b_ptr0 + (size_t)k0 * D_OUT);
            rb1 = *(const float4*)(b_ptr1 + (size_t)k0 * D_OUT);
        }

        // compute from buffer cur
        {
            const __half* buf = smem_buf[cur];
            uint32_t a[2][4];
#pragma unroll
            for (int im = 0; im < 2; im++) {
                const int mrow = wm + (im << 4) + (lane & 15);
                const int kcol = (lane >> 4) << 3;
                ldmatrix_x4(a[im], &buf[OFF_A + mrow * LDA + kcol]);
            }
#pragma unroll
            for (int jn2 = 0; jn2 < 4; jn2++) {
                const int krow = lane & 15;
                const int ncol = wn + (jn2 << 4) + ((lane >> 4) << 3);
                uint32_t bfr[4];
                ldmatrix_x4_trans(bfr, &buf[OFF_B + krow * LDB + ncol]);
#pragma unroll
                for (int im = 0; im < 2; im++) {
#pragma unroll
                    for (int j = 0; j < 2; j++) {
                        mma_f16(acc[im][(jn2 << 1) + j], a[im],
                                bfr[2 * j], bfr[2 * j + 1]);
                    }
                }
            }
        }

        // R2S into other buffer; ONE barrier per iter
        if (it + 1 < NITER) {
            __half* buf = smem_buf[cur ^ 1];
            uint32_t h[2];
            cvt4(ra0, h);
            ((uint32_t*)&buf[OFF_A + a_row0 * LDA + a_kq0])[0] = h[0];
            ((uint32_t*)&buf[OFF_A + a_row0 * LDA + a_kq0])[1] = h[1];
            cvt4(ra1, h);
            ((uint32_t*)&buf[OFF_A + a_row1 * LDA + a_kq1])[0] = h[0];
            ((uint32_t*)&buf[OFF_A + a_row1 * LDA + a_kq1])[1] = h[1];
            cvt4(rb0, h);
            ((uint32_t*)&buf[OFF_B + b_kk0 * LDB + b_n40])[0] = h[0];
            ((uint32_t*)&buf[OFF_B + b_kk0 * LDB + b_n40])[1] = h[1];
            cvt4(rb1, h);
            ((uint32_t*)&buf[OFF_B + b_kk1 * LDB + b_n41])[0] = h[0];
            ((uint32_t*)&buf[OFF_B + b_kk1 * LDB + b_n41])[1] = h[1];
            __syncthreads();
        }
    }

    // epilogue: bias + fp16 store
    const int rq = lane >> 2;        // 0..7
    const int c2 = (lane & 3) << 1;  // 0,2,4,6
#pragma unroll
    for (int jn = 0; jn < 8; jn++) {
        const int col = wn + (jn << 3) + c2;
        const float b0 = b[col];
        const float b1 = b[col + 1];
#pragma unroll
        for (int im = 0; im < 2; im++) {
#pragma unroll
            for (int h = 0; h < 2; h++) {
                const int row = block_row + wm + (im << 4) + rq + (h << 3);
                if (row < M) {
                    __half2 v = __floats2half2_rn(acc[im][jn][2 * h + 0] + b0,
                                                  acc[im][jn][2 * h + 1] + b1);
                    *(__half2*)(g_support_h + (size_t)row * D_OUT + col) = v;
                }
            }
        }
    }
}

// ---------------------------------------------------------------------------
// CSR construction
// ---------------------------------------------------------------------------
__global__ __launch_bounds__(256) void zero_cnt_kernel(int M)
{
    int i = blockIdx.x * blockDim.x + threadIdx.x;
    if (i < M) g_cnt[i] = 0;
}

__global__ __launch_bounds__(256) void hist_kernel(
    const int* __restrict__ erow, int E)
{
    int i = blockIdx.x * blockDim.x + threadIdx.x;
    int stride = gridDim.x * blockDim.x;
    for (; i < E; i += stride)
        atomicAdd(&g_cnt[erow[i]], 1);
}

// Phase 1: per-block (1024 elems) sums
__global__ __launch_bounds__(1024) void scan1_kernel(int M)
{
    __shared__ int s[1024];
    const int t = threadIdx.x;
    const int i = blockIdx.x * 1024 + t;
    int x = (i < M) ? g_cnt[i] : 0;
    s[t] = x;
    __syncthreads();
#pragma unroll
    for (int off = 512; off > 0; off >>= 1) {
        if (t < off) s[t] += s[t + off];
        __syncthreads();
    }
    if (t == 0) g_partial[blockIdx.x] = s[0];
}

// Phase 2 (fused, shuffle-based): block-local exclusive scan + block offset.
__global__ __launch_bounds__(1024) void scan3_kernel(int M, int nb)
{
    __shared__ int warp_sums[32];
    __shared__ int s_boff;

    const int t    = threadIdx.x;
    const int lane = t & 31;
    const int wid  = t >> 5;
    const int i    = blockIdx.x * 1024 + t;

    int x = (i < M) ? g_cnt[i] : 0;

    int inc = x;
#pragma unroll
    for (int off = 1; off < 32; off <<= 1) {
        int n = __shfl_up_sync(0xFFFFFFFFu, inc, off);
        if (lane >= off) inc += n;
    }
    if (lane == 31) warp_sums[wid] = inc;

    if (wid == 1) {
        int a = 0;
        for (int j = lane; j < blockIdx.x; j += 32) a += g_partial[j];
#pragma unroll
        for (int off = 16; off > 0; off >>= 1)
            a += __shfl_down_sync(0xFFFFFFFFu, a, off);
        if (lane == 0) s_boff = a;
    }
    __syncthreads();

    if (wid == 0) {
        int ws = warp_sums[lane];
        int wsi = ws;
#pragma unroll
        for (int off = 1; off < 32; off <<= 1) {
            int n = __shfl_up_sync(0xFFFFFFFFu, wsi, off);
            if (lane >= off) wsi += n;
        }
        warp_sums[lane] = wsi - ws;
    }
    __syncthreads();

    if (i < M) {
        int excl = s_boff + warp_sums[wid] + inc - x;
        g_rowstart[i] = excl;
        g_cur[i]      = excl;
    }
}

__global__ __launch_bounds__(256) void build_kernel(
    const int*   __restrict__ erow,
    const int*   __restrict__ ecol,
    const float* __restrict__ eval,
    int E)
{
    int i = blockIdx.x * blockDim.x + threadIdx.x;
    int stride = gridDim.x * blockDim.x;
    for (; i < E; i += stride) {
        int r = erow[i];
        int pos = atomicAdd(&g_cur[r], 1);
        g_epack[pos] = make_int2(ecol[i], __float_as_int(eval[i]));
    }
}

// ---------------------------------------------------------------------------
// Aggregation: one warp per row, packed-f32x2 FMAs, packed edge loads,
// cheap tanh via __expf. fp32 accumulate, fused store.
// ---------------------------------------------------------------------------
#define FMA2(accv, vv, mv) \
    asm("fma.rn.f32x2 %0, %1, %2, %0;" : "+l"(accv) : "l"(vv), "l"(mv))

__device__ __forceinline__ float fast_tanh(float x)
{
    float e = __expf(2.0f * x);
    return 1.0f - __fdividef(2.0f, e + 1.0f);
}

__global__ __launch_bounds__(256) void row_agg_kernel(
    float* __restrict__ out, int M)
{
    const int row  = (int)((blockIdx.x * blockDim.x + threadIdx.x) >> 5);
    const int lane = threadIdx.x & 31;
    if (row >= M) return;

    const int start = g_rowstart[row];
    const int end   = start + g_cnt[row];
    const size_t loff = (size_t)(lane << 2);   // 4 cols per lane

    unsigned long long acc0, acc1;             // packed f32x2 accumulators
    asm("mov.b64 %0, {%1,%2};" : "=l"(acc0) : "f"(0.0f), "f"(0.0f));
    acc1 = acc0;

    int e = start;
    for (; e + 3 < end; e += 4) {
        const int2 p0 = g_epack[e];
        const int2 p1 = g_epack[e + 1];
        const int2 p2 = g_epack[e + 2];
        const int2 p3 = g_epack[e + 3];
        uint2 u0 = *(const uint2*)(g_support_h + (size_t)p0.x * D_OUT + loff);
        uint2 u1 = *(const uint2*)(g_support_h + (size_t)p1.x * D_OUT + loff);
        uint2 u2 = *(const uint2*)(g_support_h + (size_t)p2.x * D_OUT + loff);
        uint2 u3 = *(const uint2*)(g_support_h + (size_t)p3.x * D_OUT + loff);
#pragma unroll
        for (int q = 0; q < 4; q++) {
            const int2  p = (q == 0) ? p0 : (q == 1) ? p1 : (q == 2) ? p2 : p3;
            const uint2 u = (q == 0) ? u0 : (q == 1) ? u1 : (q == 2) ? u2 : u3;
            const float v = __int_as_float(p.y);
            float2 f0 = __half22float2(*(__half2*)&u.x);
            float2 f1 = __half22float2(*(__half2*)&u.y);
            unsigned long long vv, m0, m1;
            asm("mov.b64 %0, {%1,%2};" : "=l"(vv) : "f"(v),    "f"(v));
            asm("mov.b64 %0, {%1,%2};" : "=l"(m0) : "f"(f0.x), "f"(f0.y));
            asm("mov.b64 %0, {%1,%2};" : "=l"(m1) : "f"(f1.x), "f"(f1.y));
            FMA2(acc0, vv, m0);
            FMA2(acc1, vv, m1);
        }
    }
    for (; e < end; e++) {
        const int2 p = g_epack[e];
        const float v = __int_as_float(p.y);
        uint2 u = *(const uint2*)(g_support_h + (size_t)p.x * D_OUT + loff);
        float2 f0 = __half22float2(*(__half2*)&u.x);
        float2 f1 = __half22float2(*(__half2*)&u.y);
        unsigned long long vv, m0, m1;
        asm("mov.b64 %0, {%1,%2};" : "=l"(vv) : "f"(v),    "f"(v));
        asm("mov.b64 %0, {%1,%2};" : "=l"(m0) : "f"(f0.x), "f"(f0.y));
        asm("mov.b64 %0, {%1,%2};" : "=l"(m1) : "f"(f1.x), "f"(f1.y));
        FMA2(acc0, vv, m0);
        FMA2(acc1, vv, m1);
    }

    float a0, a1, a2, a3;
    asm("mov.b64 {%0,%1}, %2;" : "=f"(a0), "=f"(a1) : "l"(acc0));
    asm("mov.b64 {%0,%1}, %2;" : "=f"(a2), "=f"(a3) : "l"(acc1));

    float4 r;
    r.x = fast_tanh(a0);
    r.y = fast_tanh(a1);
    r.z = fast_tanh(a2);
    r.w = fast_tanh(a3);
    *(float4*)(out + (size_t)row * D_OUT + loff) = r;
}

// ---------------------------------------------------------------------------
// Launch. Pure kernel launches on stream 0 — graph-capturable, no allocs.
// inputs: 0=input [N,256] f32, 1=edge_row [E] i32, 2=edge_col [E] i32,
//         3=edge_val [E] f32, 4=W [256,128] f32, 5=b [128] f32
// ---------------------------------------------------------------------------
extern "C" void kernel_launch(void* const* d_in, const int* in_sizes, int n_in,
                              void* d_out, int out_size)
{
    const float* input    = (const float*)d_in[0];
    const int*   edge_row = (const int*)  d_in[1];
    const int*   edge_col = (const int*)  d_in[2];
    const float* edge_val = (const float*)d_in[3];
    const float* W        = (const float*)d_in[4];
    const float* b        = (const float*)d_in[5];
    float*       out      = (float*)d_out;

    const int M = in_sizes[0] / D_IN;   // 100000
    const int E = in_sizes[1];          // 1600000
    const int nb = (M + 1023) / 1024;   // scan blocks (98)

    // CSR build
    zero_cnt_kernel<<<(M + 255) / 256, 256, 0, 0>>>(M);
    hist_kernel<<<1184, 256, 0, 0>>>(edge_row, E);
    scan1_kernel<<<nb, 1024, 0, 0>>>(M);
    scan3_kernel<<<nb, 1024, 0, 0>>>(M, nb);
    build_kernel<<<1184, 256, 0, 0>>>(edge_row, edge_col, edge_val, E);

    // Dense: support = input @ W + b  (fp16 tensor cores)
    gemm_bias_kernel<<<(M + BM - 1) / BM, 256, 0, 0>>>(input, W, b, M);

    // Aggregate + tanh + store (warp per row)
    {
        const long long total_threads = (long long)M * 32;
        const int blocks = (int)((total_threads + 255) / 256);
        row_agg_kernel<<<blocks, 256, 0, 0>>>(out, M);
    }
}